// round 1
// baseline (speedup 1.0000x reference)
#include <cuda_runtime.h>
#include <math.h>

// ---------------------------------------------------------------------------
// Model_19104014532987: 2-layer transformer
// B=8 T=2048 DKQ=64 DV=64 EKQ=EV=128 H=4 dh=32 FF=512 OUT=32
// R = B*T = 16384 rows
// ---------------------------------------------------------------------------

#define R_TOTAL 16384
#define T_SEQ   2048
#define EMB     128
#define NHEAD   4
#define DHEAD   32
#define FFDIM   512
#define OUTDIM  32

// Scratch pool: 34M floats (136 MB), static device allocation (allowed).
static __device__ float g_scratch[34ull * 1024 * 1024];

__device__ __forceinline__ float gelu_exact(float x) {
    return 0.5f * x * (1.0f + erff(x * 0.70710678118654752440f));
}

// ---------------------------------------------------------------------------
// concat X = [kq | v]  (R x 128)
// ---------------------------------------------------------------------------
__global__ void concat_k(const float* __restrict__ kq, const float* __restrict__ v,
                         float* __restrict__ X) {
    int r = blockIdx.x;
    int d = threadIdx.x;  // 128
    float val = (d < 64) ? kq[(size_t)r * 64 + d] : v[(size_t)r * 64 + (d - 64)];
    X[(size_t)r * 128 + d] = val;
}

// ---------------------------------------------------------------------------
// SGEMM: C[M,N] = A[M,K] @ W[K,N] + bias  (+ optional exact GELU)
// BM=BN=128, BK=16, 256 threads, 8x8 microtile.
// M must be a multiple of 128 (it is: 16384). N guarded.
// ---------------------------------------------------------------------------
__global__ __launch_bounds__(256) void sgemm_k(
    const float* __restrict__ A, const float* __restrict__ W,
    const float* __restrict__ bias, float* __restrict__ C,
    int M, int N, int K, int act)
{
    __shared__ float As[16][132];
    __shared__ float Ws[16][132];
    const int bm = blockIdx.y * 128;
    const int bn = blockIdx.x * 128;
    const int tid = threadIdx.x;
    const int tm = tid >> 4;   // 0..15
    const int tn = tid & 15;   // 0..15

    float acc[8][8];
#pragma unroll
    for (int x = 0; x < 8; x++)
#pragma unroll
        for (int y = 0; y < 8; y++) acc[x][y] = 0.f;

    for (int k0 = 0; k0 < K; k0 += 16) {
        // load A tile: 128 rows x 16 k
#pragma unroll
        for (int i = tid; i < 2048; i += 256) {
            int m = i >> 4, kk = i & 15;
            As[kk][m] = A[(size_t)(bm + m) * K + (k0 + kk)];
        }
        // load W tile: 16 k x 128 n (guarded on N)
#pragma unroll
        for (int i = tid; i < 2048; i += 256) {
            int kk = i >> 7, n = i & 127;
            int gn = bn + n;
            Ws[kk][n] = (gn < N) ? W[(size_t)(k0 + kk) * N + gn] : 0.f;
        }
        __syncthreads();
#pragma unroll
        for (int kk = 0; kk < 16; kk++) {
            float4 a0 = *reinterpret_cast<const float4*>(&As[kk][tm * 8]);
            float4 a1 = *reinterpret_cast<const float4*>(&As[kk][tm * 8 + 4]);
            float4 w0 = *reinterpret_cast<const float4*>(&Ws[kk][tn * 8]);
            float4 w1 = *reinterpret_cast<const float4*>(&Ws[kk][tn * 8 + 4]);
            float a[8] = {a0.x, a0.y, a0.z, a0.w, a1.x, a1.y, a1.z, a1.w};
            float w[8] = {w0.x, w0.y, w0.z, w0.w, w1.x, w1.y, w1.z, w1.w};
#pragma unroll
            for (int x = 0; x < 8; x++)
#pragma unroll
                for (int y = 0; y < 8; y++) acc[x][y] = fmaf(a[x], w[y], acc[x][y]);
        }
        __syncthreads();
    }

#pragma unroll
    for (int x = 0; x < 8; x++) {
        int gm = bm + tm * 8 + x;
#pragma unroll
        for (int y = 0; y < 8; y++) {
            int gn = bn + tn * 8 + y;
            if (gn < N) {
                float vv = acc[x][y] + bias[gn];
                if (act) vv = gelu_exact(vv);
                C[(size_t)gm * N + gn] = vv;
            }
        }
    }
}

// ---------------------------------------------------------------------------
// Flash attention: per (b,h), 64-query x 64-key tiles, dh=32, online softmax.
// Layout: Q/K/V/O are [B,T,128] with head h at cols h*32..h*32+31.
// mode 0: j <= i (layer A causal).  mode 1: j < i OR (i==0 && j==0) (layer B).
// 256 threads: 64 rows x 4 col-groups (16 keys each).
// ---------------------------------------------------------------------------
__global__ __launch_bounds__(256) void attn_k(
    const float* __restrict__ Q, const float* __restrict__ K,
    const float* __restrict__ V, float* __restrict__ O, int mode)
{
    const int E = EMB;
    int bh = blockIdx.y;
    size_t base = (size_t)(bh >> 2) * T_SEQ * E + (size_t)(bh & 3) * DHEAD;
    int q0 = blockIdx.x * 64;

    __shared__ float Qs[64][33];
    __shared__ float Ks[64][33];
    __shared__ float Vs[64][33];

    int tid = threadIdx.x;
    int r = tid >> 2;   // query row within tile
    int g = tid & 3;    // col group (16 keys)
    int iq = q0 + r;

    for (int i = tid; i < 64 * 32; i += 256) {
        int m = i >> 5, d = i & 31;
        Qs[m][d] = Q[base + (size_t)(q0 + m) * E + d];
    }
    __syncthreads();

    float qreg[32];
#pragma unroll
    for (int d = 0; d < 32; d++) qreg[d] = Qs[r][d];

    const float NEGINF = __int_as_float(0xff800000);
    float m_i = NEGINF, l_i = 0.f;
    float o[32];
#pragma unroll
    for (int d = 0; d < 32; d++) o[d] = 0.f;

    for (int j0 = 0; j0 <= q0; j0 += 64) {
        __syncthreads();
        for (int i = tid; i < 64 * 32; i += 256) {
            int n = i >> 5, d = i & 31;
            Ks[n][d] = K[base + (size_t)(j0 + n) * E + d];
            Vs[n][d] = V[base + (size_t)(j0 + n) * E + d];
        }
        __syncthreads();

        float s[16];
        float mloc = NEGINF;
#pragma unroll
        for (int c = 0; c < 16; c++) {
            int j = j0 + g * 16 + c;
            float acc = 0.f;
#pragma unroll
            for (int d = 0; d < 32; d++) acc = fmaf(qreg[d], Ks[g * 16 + c][d], acc);
            bool ok = (mode == 0) ? (j <= iq) : ((j < iq) || (iq == 0 && j == 0));
            s[c] = ok ? acc : NEGINF;
            mloc = fmaxf(mloc, s[c]);
        }
        // row max across the 4 threads of this row (aligned lane groups of 4)
        mloc = fmaxf(mloc, __shfl_xor_sync(0xffffffffu, mloc, 1));
        mloc = fmaxf(mloc, __shfl_xor_sync(0xffffffffu, mloc, 2));
        float m_new = fmaxf(m_i, mloc);
        float scale = __expf(m_i - m_new);  // first tile always has a valid key -> m_new finite

        float lloc = 0.f;
        float p[16];
#pragma unroll
        for (int c = 0; c < 16; c++) {
            p[c] = __expf(s[c] - m_new);  // exp(-inf - finite) = 0 for masked
            lloc += p[c];
        }
        l_i = l_i * scale + lloc;
#pragma unroll
        for (int d = 0; d < 32; d++) o[d] *= scale;
#pragma unroll
        for (int c = 0; c < 16; c++) {
            float pc = p[c];
#pragma unroll
            for (int d = 0; d < 32; d++) o[d] = fmaf(pc, Vs[g * 16 + c][d], o[d]);
        }
        m_i = m_new;
    }

    // combine partials across the 4 col-group threads
    l_i += __shfl_xor_sync(0xffffffffu, l_i, 1);
    l_i += __shfl_xor_sync(0xffffffffu, l_i, 2);
    float inv = 1.f / l_i;
#pragma unroll
    for (int d = 0; d < 32; d++) {
        o[d] += __shfl_xor_sync(0xffffffffu, o[d], 1);
        o[d] += __shfl_xor_sync(0xffffffffu, o[d], 2);
    }
#pragma unroll
    for (int d = 0; d < 8; d++) {
        O[base + (size_t)iq * E + g * 8 + d] = o[g * 8 + d] * inv;
    }
}

// ---------------------------------------------------------------------------
// out = LayerNorm(A + B) * gamma + beta, row dim 128, eps 1e-5
// one block per row, 128 threads
// ---------------------------------------------------------------------------
__global__ void add_ln_k(const float* __restrict__ A, const float* __restrict__ Bv,
                         const float* __restrict__ gam, const float* __restrict__ bet,
                         float* __restrict__ out)
{
    int row = blockIdx.x;
    int d = threadIdx.x;  // 128
    float x = A[(size_t)row * 128 + d] + Bv[(size_t)row * 128 + d];

    __shared__ float ws[4], ws2[4];
    float v = x;
#pragma unroll
    for (int off = 16; off; off >>= 1) v += __shfl_xor_sync(0xffffffffu, v, off);
    if ((d & 31) == 0) ws[d >> 5] = v;
    __syncthreads();
    float mean = (ws[0] + ws[1] + ws[2] + ws[3]) * (1.f / 128.f);
    float dif = x - mean;
    float v2 = dif * dif;
#pragma unroll
    for (int off = 16; off; off >>= 1) v2 += __shfl_xor_sync(0xffffffffu, v2, off);
    if ((d & 31) == 0) ws2[d >> 5] = v2;
    __syncthreads();
    float var = (ws2[0] + ws2[1] + ws2[2] + ws2[3]) * (1.f / 128.f);
    out[(size_t)row * 128 + d] = dif * rsqrtf(var + 1e-5f) * gam[d] + bet[d];
}

// ---------------------------------------------------------------------------
extern "C" void kernel_launch(void* const* d_in, const int* in_sizes, int n_in,
                              void* d_out, int out_size)
{
    const float* kq    = (const float*)d_in[0];
    const float* v_in  = (const float*)d_in[1];
    const float* A_Wk  = (const float*)d_in[2];
    const float* A_bk  = (const float*)d_in[3];
    const float* A_Wq  = (const float*)d_in[4];
    const float* A_bq  = (const float*)d_in[5];
    const float* A_Wv  = (const float*)d_in[6];
    const float* A_bv  = (const float*)d_in[7];
    const float* A_f1W = (const float*)d_in[8];
    const float* A_f1b = (const float*)d_in[9];
    const float* A_f2W = (const float*)d_in[10];
    const float* A_f2b = (const float*)d_in[11];
    const float* A_n1g = (const float*)d_in[12];
    const float* A_n1b = (const float*)d_in[13];
    const float* A_n2g = (const float*)d_in[14];
    const float* A_n2b = (const float*)d_in[15];
    const float* B_Wk  = (const float*)d_in[16];
    const float* B_bk  = (const float*)d_in[17];
    const float* B_Wq  = (const float*)d_in[18];
    const float* B_bq  = (const float*)d_in[19];
    const float* B_Wv  = (const float*)d_in[20];
    const float* B_bv  = (const float*)d_in[21];
    const float* B_f1W = (const float*)d_in[22];
    const float* B_f1b = (const float*)d_in[23];
    const float* B_f2W = (const float*)d_in[24];
    const float* B_f2b = (const float*)d_in[25];
    const float* out_W = (const float*)d_in[26];
    const float* out_b = (const float*)d_in[27];
    float* out = (float*)d_out;

    float* pool = nullptr;
    cudaGetSymbolAddress((void**)&pool, g_scratch);

    const size_t S128 = (size_t)R_TOTAL * 128;  // 2M floats
    float* X     = pool + 0 * S128;
    float* Ka    = pool + 1 * S128;
    float* Qa    = pool + 2 * S128;
    float* Va    = pool + 3 * S128;
    float* attnA = pool + 4 * S128;
    float* h1    = pool + 5 * S128;
    float* t1    = pool + 6 * S128;
    float* vA    = pool + 7 * S128;
    float* K2    = pool + 8 * S128;
    float* Q2    = pool + 9 * S128;
    float* V2    = pool + 10 * S128;
    float* attn2 = pool + 11 * S128;
    float* ffb   = pool + 12 * S128;
    float* ff    = pool + 13 * S128;  // R x 512 (4 slots)

    dim3 blk256(256);
    dim3 gridN128(1, R_TOTAL / 128);           // N=128 GEMMs
    dim3 gridN512(4, R_TOTAL / 128);           // N=512 GEMMs
    dim3 gridN32(1, R_TOTAL / 128);            // N=32 GEMM
    dim3 attnGrid(T_SEQ / 64, 8 * NHEAD);      // (32, 32)

    // ---- Layer A ----
    concat_k<<<R_TOTAL, 128>>>(kq, v_in, X);
    sgemm_k<<<gridN128, blk256>>>(X, A_Wk, A_bk, Ka, R_TOTAL, 128, 128, 0);
    sgemm_k<<<gridN128, blk256>>>(X, A_Wq, A_bq, Qa, R_TOTAL, 128, 128, 0);
    sgemm_k<<<gridN128, blk256>>>(X, A_Wv, A_bv, Va, R_TOTAL, 128, 128, 0);
    attn_k<<<attnGrid, blk256>>>(Qa, Ka, Va, attnA, 0);
    add_ln_k<<<R_TOTAL, 128>>>(Va, attnA, A_n1g, A_n1b, h1);
    sgemm_k<<<gridN512, blk256>>>(h1, A_f1W, A_f1b, ff, R_TOTAL, 512, 128, 1);
    sgemm_k<<<gridN128, blk256>>>(ff, A_f2W, A_f2b, t1, R_TOTAL, 128, 512, 0);
    add_ln_k<<<R_TOTAL, 128>>>(h1, t1, A_n2g, A_n2b, vA);

    // ---- Layer B ----
    sgemm_k<<<gridN128, blk256>>>(kq, B_Wk, B_bk, K2, R_TOTAL, 128, 64, 0);
    sgemm_k<<<gridN128, blk256>>>(kq, B_Wq, B_bq, Q2, R_TOTAL, 128, 64, 0);
    sgemm_k<<<gridN128, blk256>>>(vA, B_Wv, B_bv, V2, R_TOTAL, 128, 128, 0);
    attn_k<<<attnGrid, blk256>>>(Q2, K2, V2, attn2, 1);
    sgemm_k<<<gridN512, blk256>>>(attn2, B_f1W, B_f1b, ff, R_TOTAL, 512, 128, 1);
    sgemm_k<<<gridN128, blk256>>>(ff, B_f2W, B_f2b, ffb, R_TOTAL, 128, 512, 0);
    sgemm_k<<<gridN32, blk256>>>(ffb, out_W, out_b, out, R_TOTAL, 32, 128, 0);
}

// round 2
// speedup vs baseline: 2.3550x; 2.3550x over previous
#include <cuda_runtime.h>
#include <math.h>

// ---------------------------------------------------------------------------
// Model_19104014532987: 2-layer transformer
// B=8 T=2048 DKQ=64 DV=64 EKQ=EV=128 H=4 dh=32 FF=512 OUT=32
// R = B*T = 16384 rows
// ---------------------------------------------------------------------------

#define R_TOTAL 16384
#define T_SEQ   2048
#define EMB     128
#define NHEAD   4
#define DHEAD   32
#define FFDIM   512
#define OUTDIM  32

// Scratch pool: 34M floats (136 MB), static device allocation (allowed).
static __device__ float g_scratch[34ull * 1024 * 1024];

__device__ __forceinline__ float gelu_exact(float x) {
    return 0.5f * x * (1.0f + erff(x * 0.70710678118654752440f));
}

// ---------------------------------------------------------------------------
// concat X = [kq | v]  (R x 128)
// ---------------------------------------------------------------------------
__global__ void concat_k(const float* __restrict__ kq, const float* __restrict__ v,
                         float* __restrict__ X) {
    int r = blockIdx.x;
    int d = threadIdx.x;  // 128
    float val = (d < 64) ? kq[(size_t)r * 64 + d] : v[(size_t)r * 64 + (d - 64)];
    X[(size_t)r * 128 + d] = val;
}

// ---------------------------------------------------------------------------
// SGEMM: C[M,N] = A[M,K] @ W[K,N] + bias  (+ optional exact GELU)
// BM=BN=128, BK=16, 256 threads, 8x8 microtile.
// ---------------------------------------------------------------------------
__global__ __launch_bounds__(256) void sgemm_k(
    const float* __restrict__ A, const float* __restrict__ W,
    const float* __restrict__ bias, float* __restrict__ C,
    int M, int N, int K, int act)
{
    __shared__ float As[16][132];
    __shared__ float Ws[16][132];
    const int bm = blockIdx.y * 128;
    const int bn = blockIdx.x * 128;
    const int tid = threadIdx.x;
    const int tm = tid >> 4;   // 0..15
    const int tn = tid & 15;   // 0..15

    float acc[8][8];
#pragma unroll
    for (int x = 0; x < 8; x++)
#pragma unroll
        for (int y = 0; y < 8; y++) acc[x][y] = 0.f;

    for (int k0 = 0; k0 < K; k0 += 16) {
#pragma unroll
        for (int i = tid; i < 2048; i += 256) {
            int m = i >> 4, kk = i & 15;
            As[kk][m] = A[(size_t)(bm + m) * K + (k0 + kk)];
        }
#pragma unroll
        for (int i = tid; i < 2048; i += 256) {
            int kk = i >> 7, n = i & 127;
            int gn = bn + n;
            Ws[kk][n] = (gn < N) ? W[(size_t)(k0 + kk) * N + gn] : 0.f;
        }
        __syncthreads();
#pragma unroll
        for (int kk = 0; kk < 16; kk++) {
            float4 a0 = *reinterpret_cast<const float4*>(&As[kk][tm * 8]);
            float4 a1 = *reinterpret_cast<const float4*>(&As[kk][tm * 8 + 4]);
            float4 w0 = *reinterpret_cast<const float4*>(&Ws[kk][tn * 8]);
            float4 w1 = *reinterpret_cast<const float4*>(&Ws[kk][tn * 8 + 4]);
            float a[8] = {a0.x, a0.y, a0.z, a0.w, a1.x, a1.y, a1.z, a1.w};
            float w[8] = {w0.x, w0.y, w0.z, w0.w, w1.x, w1.y, w1.z, w1.w};
#pragma unroll
            for (int x = 0; x < 8; x++)
#pragma unroll
                for (int y = 0; y < 8; y++) acc[x][y] = fmaf(a[x], w[y], acc[x][y]);
        }
        __syncthreads();
    }

#pragma unroll
    for (int x = 0; x < 8; x++) {
        int gm = bm + tm * 8 + x;
#pragma unroll
        for (int y = 0; y < 8; y++) {
            int gn = bn + tn * 8 + y;
            if (gn < N) {
                float vv = acc[x][y] + bias[gn];
                if (act) vv = gelu_exact(vv);
                C[(size_t)gm * N + gn] = vv;
            }
        }
    }
}

// ---------------------------------------------------------------------------
// Flash attention v2: per (b,h), 64-query x 64-key tiles, dh=32, online softmax.
// 256 threads = 32 row-pairs x 8 key-groups. Each thread: 2 query rows (regs),
// 8 keys. K/V in smem [64][32] with XOR-quad swizzle (quad ^= row>>3) so the
// 8 key-groups of a warp hit 8 distinct bank-quads -> conflict-free LDS.128.
// FMA:LDS.128 ratio = 8:1 in both QK and PV loops.
// mode 0: j <= i.  mode 1: j < i OR (i==0 && j==0).
// ---------------------------------------------------------------------------
__global__ __launch_bounds__(256) void attn_k(
    const float* __restrict__ Q, const float* __restrict__ K,
    const float* __restrict__ V, float* __restrict__ O, int mode)
{
    const int E = EMB;
    int bh = blockIdx.y;
    size_t base = (size_t)(bh >> 2) * T_SEQ * E + (size_t)(bh & 3) * DHEAD;
    // heavy blocks (large q0) first
    int q0 = (gridDim.x - 1 - blockIdx.x) * 64;

    __shared__ float Ks[64 * 32];
    __shared__ float Vs[64 * 32];

    const int tid = threadIdx.x;
    const int rp = tid >> 3;   // 0..31 row-pair
    const int g  = tid & 7;    // 0..7 key-group
    const int i0 = q0 + rp * 2;
    const int i1 = i0 + 1;

    // Q rows -> registers (direct from global, float4)
    float q0r[32], q1r[32];
#pragma unroll
    for (int d4 = 0; d4 < 8; d4++) {
        float4 a = *reinterpret_cast<const float4*>(&Q[base + (size_t)i0 * E + d4 * 4]);
        float4 b = *reinterpret_cast<const float4*>(&Q[base + (size_t)i1 * E + d4 * 4]);
        q0r[d4*4+0] = a.x; q0r[d4*4+1] = a.y; q0r[d4*4+2] = a.z; q0r[d4*4+3] = a.w;
        q1r[d4*4+0] = b.x; q1r[d4*4+1] = b.y; q1r[d4*4+2] = b.z; q1r[d4*4+3] = b.w;
    }

    const float NEGINF = __int_as_float(0xff800000);
    float m0 = NEGINF, m1 = NEGINF, l0 = 0.f, l1 = 0.f;
    float o0[32], o1[32];
#pragma unroll
    for (int d = 0; d < 32; d++) { o0[d] = 0.f; o1[d] = 0.f; }

    for (int j0 = 0; j0 <= q0; j0 += 64) {
        __syncthreads();
        // load K,V tile with swizzle: physical quad = d4 ^ (n>>3)
#pragma unroll
        for (int i = tid; i < 512; i += 256) {
            int n = i >> 3, d4 = i & 7;
            int pq = (d4 ^ (n >> 3)) << 2;
            float4 kk = *reinterpret_cast<const float4*>(&K[base + (size_t)(j0 + n) * E + d4 * 4]);
            float4 vv = *reinterpret_cast<const float4*>(&V[base + (size_t)(j0 + n) * E + d4 * 4]);
            *reinterpret_cast<float4*>(&Ks[n * 32 + pq]) = kk;
            *reinterpret_cast<float4*>(&Vs[n * 32 + pq]) = vv;
        }
        __syncthreads();

        // ---- QK ----
        float s0[8], s1[8];
        float ml0 = NEGINF, ml1 = NEGINF;
#pragma unroll
        for (int c = 0; c < 8; c++) {
            int kr = g * 8 + c;           // kr>>3 == g
            const float* krow = &Ks[kr * 32];
            float a0 = 0.f, a1 = 0.f;
#pragma unroll
            for (int d4 = 0; d4 < 8; d4++) {
                float4 kk = *reinterpret_cast<const float4*>(&krow[(d4 ^ g) << 2]);
                a0 = fmaf(q0r[d4*4+0], kk.x, a0); a1 = fmaf(q1r[d4*4+0], kk.x, a1);
                a0 = fmaf(q0r[d4*4+1], kk.y, a0); a1 = fmaf(q1r[d4*4+1], kk.y, a1);
                a0 = fmaf(q0r[d4*4+2], kk.z, a0); a1 = fmaf(q1r[d4*4+2], kk.z, a1);
                a0 = fmaf(q0r[d4*4+3], kk.w, a0); a1 = fmaf(q1r[d4*4+3], kk.w, a1);
            }
            int j = j0 + kr;
            bool ok0 = (mode == 0) ? (j <= i0) : ((j < i0) || (i0 == 0 && j == 0));
            bool ok1 = (mode == 0) ? (j <= i1) : (j < i1);
            s0[c] = ok0 ? a0 : NEGINF;
            s1[c] = ok1 ? a1 : NEGINF;
            ml0 = fmaxf(ml0, s0[c]);
            ml1 = fmaxf(ml1, s1[c]);
        }
        // row max across the 8 key-group lanes (aligned groups of 8)
        ml0 = fmaxf(ml0, __shfl_xor_sync(0xffffffffu, ml0, 1));
        ml0 = fmaxf(ml0, __shfl_xor_sync(0xffffffffu, ml0, 2));
        ml0 = fmaxf(ml0, __shfl_xor_sync(0xffffffffu, ml0, 4));
        ml1 = fmaxf(ml1, __shfl_xor_sync(0xffffffffu, ml1, 1));
        ml1 = fmaxf(ml1, __shfl_xor_sync(0xffffffffu, ml1, 2));
        ml1 = fmaxf(ml1, __shfl_xor_sync(0xffffffffu, ml1, 4));

        float mn0 = fmaxf(m0, ml0);
        float mn1 = fmaxf(m1, ml1);
        float sc0 = __expf(m0 - mn0);
        float sc1 = __expf(m1 - mn1);

        float ll0 = 0.f, ll1 = 0.f;
#pragma unroll
        for (int c = 0; c < 8; c++) {
            s0[c] = __expf(s0[c] - mn0);   // masked -> 0
            s1[c] = __expf(s1[c] - mn1);
            ll0 += s0[c]; ll1 += s1[c];
        }
        l0 = l0 * sc0 + ll0;
        l1 = l1 * sc1 + ll1;
#pragma unroll
        for (int d = 0; d < 32; d++) { o0[d] *= sc0; o1[d] *= sc1; }

        // ---- PV ----
#pragma unroll
        for (int c = 0; c < 8; c++) {
            int kr = g * 8 + c;
            const float* vrow = &Vs[kr * 32];
            float p0 = s0[c], p1 = s1[c];
#pragma unroll
            for (int d4 = 0; d4 < 8; d4++) {
                float4 vv = *reinterpret_cast<const float4*>(&vrow[(d4 ^ g) << 2]);
                o0[d4*4+0] = fmaf(p0, vv.x, o0[d4*4+0]); o1[d4*4+0] = fmaf(p1, vv.x, o1[d4*4+0]);
                o0[d4*4+1] = fmaf(p0, vv.y, o0[d4*4+1]); o1[d4*4+1] = fmaf(p1, vv.y, o1[d4*4+1]);
                o0[d4*4+2] = fmaf(p0, vv.z, o0[d4*4+2]); o1[d4*4+2] = fmaf(p1, vv.z, o1[d4*4+2]);
                o0[d4*4+3] = fmaf(p0, vv.w, o0[d4*4+3]); o1[d4*4+3] = fmaf(p1, vv.w, o1[d4*4+3]);
            }
        }
        m0 = mn0; m1 = mn1;
    }

    // combine partials across the 8 key-group lanes
    l0 += __shfl_xor_sync(0xffffffffu, l0, 1);
    l0 += __shfl_xor_sync(0xffffffffu, l0, 2);
    l0 += __shfl_xor_sync(0xffffffffu, l0, 4);
    l1 += __shfl_xor_sync(0xffffffffu, l1, 1);
    l1 += __shfl_xor_sync(0xffffffffu, l1, 2);
    l1 += __shfl_xor_sync(0xffffffffu, l1, 4);
    float inv0 = 1.f / l0;
    float inv1 = 1.f / l1;
#pragma unroll
    for (int d = 0; d < 32; d++) {
        o0[d] += __shfl_xor_sync(0xffffffffu, o0[d], 1);
        o0[d] += __shfl_xor_sync(0xffffffffu, o0[d], 2);
        o0[d] += __shfl_xor_sync(0xffffffffu, o0[d], 4);
        o1[d] += __shfl_xor_sync(0xffffffffu, o1[d], 1);
        o1[d] += __shfl_xor_sync(0xffffffffu, o1[d], 2);
        o1[d] += __shfl_xor_sync(0xffffffffu, o1[d], 4);
    }
    // lane g writes dims [g*4, g*4+4) for both rows
    float4 w0, w1;
    w0.x = o0[g*4+0] * inv0; w0.y = o0[g*4+1] * inv0; w0.z = o0[g*4+2] * inv0; w0.w = o0[g*4+3] * inv0;
    w1.x = o1[g*4+0] * inv1; w1.y = o1[g*4+1] * inv1; w1.z = o1[g*4+2] * inv1; w1.w = o1[g*4+3] * inv1;
    *reinterpret_cast<float4*>(&O[base + (size_t)i0 * E + g * 4]) = w0;
    *reinterpret_cast<float4*>(&O[base + (size_t)i1 * E + g * 4]) = w1;
}

// ---------------------------------------------------------------------------
// out = LayerNorm(A + B) * gamma + beta, row dim 128, eps 1e-5
// ---------------------------------------------------------------------------
__global__ void add_ln_k(const float* __restrict__ A, const float* __restrict__ Bv,
                         const float* __restrict__ gam, const float* __restrict__ bet,
                         float* __restrict__ out)
{
    int row = blockIdx.x;
    int d = threadIdx.x;  // 128
    float x = A[(size_t)row * 128 + d] + Bv[(size_t)row * 128 + d];

    __shared__ float ws[4], ws2[4];
    float v = x;
#pragma unroll
    for (int off = 16; off; off >>= 1) v += __shfl_xor_sync(0xffffffffu, v, off);
    if ((d & 31) == 0) ws[d >> 5] = v;
    __syncthreads();
    float mean = (ws[0] + ws[1] + ws[2] + ws[3]) * (1.f / 128.f);
    float dif = x - mean;
    float v2 = dif * dif;
#pragma unroll
    for (int off = 16; off; off >>= 1) v2 += __shfl_xor_sync(0xffffffffu, v2, off);
    if ((d & 31) == 0) ws2[d >> 5] = v2;
    __syncthreads();
    float var = (ws2[0] + ws2[1] + ws2[2] + ws2[3]) * (1.f / 128.f);
    out[(size_t)row * 128 + d] = dif * rsqrtf(var + 1e-5f) * gam[d] + bet[d];
}

// ---------------------------------------------------------------------------
extern "C" void kernel_launch(void* const* d_in, const int* in_sizes, int n_in,
                              void* d_out, int out_size)
{
    const float* kq    = (const float*)d_in[0];
    const float* v_in  = (const float*)d_in[1];
    const float* A_Wk  = (const float*)d_in[2];
    const float* A_bk  = (const float*)d_in[3];
    const float* A_Wq  = (const float*)d_in[4];
    const float* A_bq  = (const float*)d_in[5];
    const float* A_Wv  = (const float*)d_in[6];
    const float* A_bv  = (const float*)d_in[7];
    const float* A_f1W = (const float*)d_in[8];
    const float* A_f1b = (const float*)d_in[9];
    const float* A_f2W = (const float*)d_in[10];
    const float* A_f2b = (const float*)d_in[11];
    const float* A_n1g = (const float*)d_in[12];
    const float* A_n1b = (const float*)d_in[13];
    const float* A_n2g = (const float*)d_in[14];
    const float* A_n2b = (const float*)d_in[15];
    const float* B_Wk  = (const float*)d_in[16];
    const float* B_bk  = (const float*)d_in[17];
    const float* B_Wq  = (const float*)d_in[18];
    const float* B_bq  = (const float*)d_in[19];
    const float* B_Wv  = (const float*)d_in[20];
    const float* B_bv  = (const float*)d_in[21];
    const float* B_f1W = (const float*)d_in[22];
    const float* B_f1b = (const float*)d_in[23];
    const float* B_f2W = (const float*)d_in[24];
    const float* B_f2b = (const float*)d_in[25];
    const float* out_W = (const float*)d_in[26];
    const float* out_b = (const float*)d_in[27];
    float* out = (float*)d_out;

    float* pool = nullptr;
    cudaGetSymbolAddress((void**)&pool, g_scratch);

    const size_t S128 = (size_t)R_TOTAL * 128;  // 2M floats
    float* X     = pool + 0 * S128;
    float* Ka    = pool + 1 * S128;
    float* Qa    = pool + 2 * S128;
    float* Va    = pool + 3 * S128;
    float* attnA = pool + 4 * S128;
    float* h1    = pool + 5 * S128;
    float* t1    = pool + 6 * S128;
    float* vA    = pool + 7 * S128;
    float* K2    = pool + 8 * S128;
    float* Q2    = pool + 9 * S128;
    float* V2    = pool + 10 * S128;
    float* attn2 = pool + 11 * S128;
    float* ffb   = pool + 12 * S128;
    float* ff    = pool + 13 * S128;  // R x 512 (4 slots)

    dim3 blk256(256);
    dim3 gridN128(1, R_TOTAL / 128);           // N=128 GEMMs
    dim3 gridN512(4, R_TOTAL / 128);           // N=512 GEMMs
    dim3 gridN32(1, R_TOTAL / 128);            // N=32 GEMM
    dim3 attnGrid(T_SEQ / 64, 8 * NHEAD);      // (32, 32)

    // ---- Layer A ----
    concat_k<<<R_TOTAL, 128>>>(kq, v_in, X);
    sgemm_k<<<gridN128, blk256>>>(X, A_Wk, A_bk, Ka, R_TOTAL, 128, 128, 0);
    sgemm_k<<<gridN128, blk256>>>(X, A_Wq, A_bq, Qa, R_TOTAL, 128, 128, 0);
    sgemm_k<<<gridN128, blk256>>>(X, A_Wv, A_bv, Va, R_TOTAL, 128, 128, 0);
    attn_k<<<attnGrid, blk256>>>(Qa, Ka, Va, attnA, 0);
    add_ln_k<<<R_TOTAL, 128>>>(Va, attnA, A_n1g, A_n1b, h1);
    sgemm_k<<<gridN512, blk256>>>(h1, A_f1W, A_f1b, ff, R_TOTAL, 512, 128, 1);
    sgemm_k<<<gridN128, blk256>>>(ff, A_f2W, A_f2b, t1, R_TOTAL, 128, 512, 0);
    add_ln_k<<<R_TOTAL, 128>>>(h1, t1, A_n2g, A_n2b, vA);

    // ---- Layer B ----
    sgemm_k<<<gridN128, blk256>>>(kq, B_Wk, B_bk, K2, R_TOTAL, 128, 64, 0);
    sgemm_k<<<gridN128, blk256>>>(kq, B_Wq, B_bq, Q2, R_TOTAL, 128, 64, 0);
    sgemm_k<<<gridN128, blk256>>>(vA, B_Wv, B_bv, V2, R_TOTAL, 128, 128, 0);
    attn_k<<<attnGrid, blk256>>>(Q2, K2, V2, attn2, 1);
    sgemm_k<<<gridN512, blk256>>>(attn2, B_f1W, B_f1b, ff, R_TOTAL, 512, 128, 1);
    sgemm_k<<<gridN128, blk256>>>(ff, B_f2W, B_f2b, ffb, R_TOTAL, 128, 512, 0);
    sgemm_k<<<gridN32, blk256>>>(ffb, out_W, out_b, out, R_TOTAL, 32, 128, 0);
}

// round 5
// speedup vs baseline: 2.9893x; 1.2693x over previous
#include <cuda_runtime.h>
#include <cuda_bf16.h>
#include <math.h>
#include <stdint.h>

// ---------------------------------------------------------------------------
// Model_19104014532987: 2-layer transformer
// B=8 T=2048 DKQ=64 DV=64 EKQ=EV=128 H=4 dh=32 FF=512 OUT=32
// R = B*T = 16384 rows
// GEMMs: mma.sync bf16 (HMMA) with bf16x3 split precision. Attention fp32.
// (tcgen05 is unavailable: harness PTX target is sm_103 without the 'a'.)
// ---------------------------------------------------------------------------

#define R_TOTAL 16384
#define T_SEQ   2048
#define EMB     128
#define NHEAD   4
#define DHEAD   32

// Scratch pool: 44M floats (176 MB), static device allocation (allowed).
static __device__ __align__(256) float g_scratch[44ull * 1024 * 1024];

__device__ __forceinline__ float gelu_exact(float x) {
    return 0.5f * x * (1.0f + erff(x * 0.70710678118654752440f));
}

__device__ __forceinline__ uint32_t smem_u32(const void* p) {
    uint32_t a;
    asm("{ .reg .u64 t; cvta.to.shared.u64 t, %1; cvt.u32.u64 %0, t; }" : "=r"(a) : "l"(p));
    return a;
}

#define LDMX4(r0, r1, r2, r3, addr) \
    asm volatile("ldmatrix.sync.aligned.m8n8.x4.shared.b16 {%0,%1,%2,%3}, [%4];" \
        : "=r"(r0), "=r"(r1), "=r"(r2), "=r"(r3) : "r"(addr))

#define MMA16816(d, a, b0, b1) \
    asm volatile("mma.sync.aligned.m16n8k16.row.col.f32.bf16.bf16.f32 " \
        "{%0,%1,%2,%3}, {%4,%5,%6,%7}, {%8,%9}, {%0,%1,%2,%3};" \
        : "+f"((d)[0]), "+f"((d)[1]), "+f"((d)[2]), "+f"((d)[3]) \
        : "r"((a)[0]), "r"((a)[1]), "r"((a)[2]), "r"((a)[3]), "r"(b0), "r"(b1))

// ---------------------------------------------------------------------------
// split: fp32 -> bf16 hi + bf16 lo   (vectorized by 4)
// ---------------------------------------------------------------------------
__global__ void split_k(const float* __restrict__ x, __nv_bfloat16* __restrict__ h,
                        __nv_bfloat16* __restrict__ l, int n4) {
    int i = blockIdx.x * 256 + threadIdx.x;
    if (i >= n4) return;
    float4 v = reinterpret_cast<const float4*>(x)[i];
    __nv_bfloat16 h0 = __float2bfloat16(v.x), h1 = __float2bfloat16(v.y);
    __nv_bfloat16 h2 = __float2bfloat16(v.z), h3 = __float2bfloat16(v.w);
    __nv_bfloat16 l0 = __float2bfloat16(v.x - __bfloat162float(h0));
    __nv_bfloat16 l1 = __float2bfloat16(v.y - __bfloat162float(h1));
    __nv_bfloat16 l2 = __float2bfloat16(v.z - __bfloat162float(h2));
    __nv_bfloat16 l3 = __float2bfloat16(v.w - __bfloat162float(h3));
    __nv_bfloat162 hh0, hh1, ll0, ll1;
    hh0.x = h0; hh0.y = h1; hh1.x = h2; hh1.y = h3;
    ll0.x = l0; ll0.y = l1; ll1.x = l2; ll1.y = l3;
    reinterpret_cast<__nv_bfloat162*>(h)[i * 2]     = hh0;
    reinterpret_cast<__nv_bfloat162*>(h)[i * 2 + 1] = hh1;
    reinterpret_cast<__nv_bfloat162*>(l)[i * 2]     = ll0;
    reinterpret_cast<__nv_bfloat162*>(l)[i * 2 + 1] = ll1;
}

// splitcat: X = [kq | v] split directly to bf16 hi/lo (no fp32 X materialized)
__global__ void splitcat_k(const float* __restrict__ kq, const float* __restrict__ v,
                           __nv_bfloat16* __restrict__ h, __nv_bfloat16* __restrict__ l) {
    int i = blockIdx.x * 256 + threadIdx.x;   // over R*128/4 = 524288
    if (i >= R_TOTAL * 32) return;
    int e = i * 4;
    int r = e >> 7, d = e & 127;
    float4 val = (d < 64)
        ? *reinterpret_cast<const float4*>(&kq[(size_t)r * 64 + d])
        : *reinterpret_cast<const float4*>(&v[(size_t)r * 64 + (d - 64)]);
    __nv_bfloat16 h0 = __float2bfloat16(val.x), h1 = __float2bfloat16(val.y);
    __nv_bfloat16 h2 = __float2bfloat16(val.z), h3 = __float2bfloat16(val.w);
    __nv_bfloat16 l0 = __float2bfloat16(val.x - __bfloat162float(h0));
    __nv_bfloat16 l1 = __float2bfloat16(val.y - __bfloat162float(h1));
    __nv_bfloat16 l2 = __float2bfloat16(val.z - __bfloat162float(h2));
    __nv_bfloat16 l3 = __float2bfloat16(val.w - __bfloat162float(h3));
    __nv_bfloat162 hh0, hh1, ll0, ll1;
    hh0.x = h0; hh0.y = h1; hh1.x = h2; hh1.y = h3;
    ll0.x = l0; ll0.y = l1; ll1.x = l2; ll1.y = l3;
    reinterpret_cast<__nv_bfloat162*>(h)[i * 2]     = hh0;
    reinterpret_cast<__nv_bfloat162*>(h)[i * 2 + 1] = hh1;
    reinterpret_cast<__nv_bfloat162*>(l)[i * 2]     = ll0;
    reinterpret_cast<__nv_bfloat162*>(l)[i * 2 + 1] = ll1;
}

// ---------------------------------------------------------------------------
// transpose+split: W[K,N] -> Wt[N,K] bf16 hi/lo
// ---------------------------------------------------------------------------
__global__ void tsplit_k(const float* __restrict__ W, __nv_bfloat16* __restrict__ th,
                         __nv_bfloat16* __restrict__ tl, int Kd, int Nd) {
    int idx = blockIdx.x * 256 + threadIdx.x;
    if (idx >= Kd * Nd) return;
    int n = idx / Kd, k = idx - n * Kd;
    float w = W[(size_t)k * Nd + n];
    __nv_bfloat16 h = __float2bfloat16(w);
    th[idx] = h;
    tl[idx] = __float2bfloat16(w - __bfloat162float(h));
}

// ---------------------------------------------------------------------------
// mma_gemm: C[128,128] tile = A[M,K] @ Wt[N,K]^T, bf16x3 split precision.
// 256 threads = 8 warps, warp tile 32x64 (warps 4x2). BK=32.
// smem: padded stride 40 bf16 (80B) -> conflict-free ldmatrix.
// Epilogue: + bias (+ optional exact GELU) -> fp32 C (row stride Nstride).
// ---------------------------------------------------------------------------
__global__ __launch_bounds__(256) void mma_gemm(
    const __nv_bfloat16* __restrict__ Ah, const __nv_bfloat16* __restrict__ Al,
    const __nv_bfloat16* __restrict__ Bh, const __nv_bfloat16* __restrict__ Bl,
    const float* __restrict__ bias, float* __restrict__ C,
    int K, int Nstride, int act)
{
    __shared__ __align__(16) __nv_bfloat16 smAh[128 * 40];
    __shared__ __align__(16) __nv_bfloat16 smAl[128 * 40];
    __shared__ __align__(16) __nv_bfloat16 smBh[128 * 40];
    __shared__ __align__(16) __nv_bfloat16 smBl[128 * 40];

    const int tid = threadIdx.x;
    const int l = tid & 31, w = tid >> 5;
    const int wm = w >> 1, wn = w & 1;
    const int bm = blockIdx.y * 128, bn = blockIdx.x * 128;

    float d[2][8][4];
#pragma unroll
    for (int mt = 0; mt < 2; mt++)
#pragma unroll
        for (int nt = 0; nt < 8; nt++)
#pragma unroll
            for (int q = 0; q < 4; q++) d[mt][nt][q] = 0.f;

    const uint32_t aAh = smem_u32(smAh), aAl = smem_u32(smAl);
    const uint32_t aBh = smem_u32(smBh), aBl = smem_u32(smBl);

    // ldmatrix lane address components (elements)
    const int a_row = wm * 32 + (l & 7) + ((l >> 3) & 1) * 8;  // + mt*16
    const int a_kof = (l >> 4) * 8;                            // + ks
    const int b_row = wn * 64 + (l >> 4) * 8 + (l & 7);        // + j*16
    const int b_kof = ((l >> 3) & 1) * 8;                      // + ks

    for (int kc = 0; kc < K; kc += 32) {
        if (kc) __syncthreads();
#pragma unroll
        for (int i = tid; i < 512; i += 256) {
            int row = i >> 2, ch = i & 3;
            size_t ga = (size_t)(bm + row) * K + kc + ch * 8;
            size_t gb = (size_t)(bn + row) * K + kc + ch * 8;
            int sa = row * 40 + ch * 8;
            *reinterpret_cast<uint4*>(smAh + sa) = *reinterpret_cast<const uint4*>(Ah + ga);
            *reinterpret_cast<uint4*>(smAl + sa) = *reinterpret_cast<const uint4*>(Al + ga);
            *reinterpret_cast<uint4*>(smBh + sa) = *reinterpret_cast<const uint4*>(Bh + gb);
            *reinterpret_cast<uint4*>(smBl + sa) = *reinterpret_cast<const uint4*>(Bl + gb);
        }
        __syncthreads();

#pragma unroll
        for (int ks = 0; ks < 32; ks += 16) {
            uint32_t ah[2][4], al2[2][4];
#pragma unroll
            for (int mt = 0; mt < 2; mt++) {
                uint32_t off = (uint32_t)(((a_row + mt * 16) * 40 + a_kof + ks) * 2);
                LDMX4(ah[mt][0], ah[mt][1], ah[mt][2], ah[mt][3], aAh + off);
                LDMX4(al2[mt][0], al2[mt][1], al2[mt][2], al2[mt][3], aAl + off);
            }
#pragma unroll
            for (int j = 0; j < 4; j++) {
                uint32_t boff = (uint32_t)(((b_row + j * 16) * 40 + b_kof + ks) * 2);
                uint32_t bh[4], bl2[4];
                LDMX4(bh[0], bh[1], bh[2], bh[3], aBh + boff);
                LDMX4(bl2[0], bl2[1], bl2[2], bl2[3], aBl + boff);
#pragma unroll
                for (int mt = 0; mt < 2; mt++) {
                    MMA16816(d[mt][2 * j],     ah[mt],  bh[0],  bh[1]);
                    MMA16816(d[mt][2 * j],     al2[mt], bh[0],  bh[1]);
                    MMA16816(d[mt][2 * j],     ah[mt],  bl2[0], bl2[1]);
                    MMA16816(d[mt][2 * j + 1], ah[mt],  bh[2],  bh[3]);
                    MMA16816(d[mt][2 * j + 1], al2[mt], bh[2],  bh[3]);
                    MMA16816(d[mt][2 * j + 1], ah[mt],  bl2[2], bl2[3]);
                }
            }
        }
    }

    // epilogue
#pragma unroll
    for (int mt = 0; mt < 2; mt++) {
        int r0 = bm + wm * 32 + mt * 16 + (l >> 2);
#pragma unroll
        for (int nt = 0; nt < 8; nt++) {
            int c = bn + wn * 64 + nt * 8 + (l & 3) * 2;
            float b0 = bias[c], b1 = bias[c + 1];
            float2 v0, v1;
            v0.x = d[mt][nt][0] + b0; v0.y = d[mt][nt][1] + b1;
            v1.x = d[mt][nt][2] + b0; v1.y = d[mt][nt][3] + b1;
            if (act) {
                v0.x = gelu_exact(v0.x); v0.y = gelu_exact(v0.y);
                v1.x = gelu_exact(v1.x); v1.y = gelu_exact(v1.y);
            }
            *reinterpret_cast<float2*>(&C[(size_t)r0 * Nstride + c]) = v0;
            *reinterpret_cast<float2*>(&C[(size_t)(r0 + 8) * Nstride + c]) = v1;
        }
    }
}

// ---------------------------------------------------------------------------
// fp32 SGEMM (only for the tiny OUT head, N=32)
// ---------------------------------------------------------------------------
__global__ __launch_bounds__(256) void sgemm_k(
    const float* __restrict__ A, const float* __restrict__ W,
    const float* __restrict__ bias, float* __restrict__ C,
    int M, int N, int K, int act)
{
    __shared__ float As[16][132];
    __shared__ float Ws[16][132];
    const int bm = blockIdx.y * 128;
    const int bn = blockIdx.x * 128;
    const int tid = threadIdx.x;
    const int tm = tid >> 4;
    const int tn = tid & 15;

    float acc[8][8];
#pragma unroll
    for (int x = 0; x < 8; x++)
#pragma unroll
        for (int y = 0; y < 8; y++) acc[x][y] = 0.f;

    for (int k0 = 0; k0 < K; k0 += 16) {
#pragma unroll
        for (int i = tid; i < 2048; i += 256) {
            int m = i >> 4, kk = i & 15;
            As[kk][m] = A[(size_t)(bm + m) * K + (k0 + kk)];
        }
#pragma unroll
        for (int i = tid; i < 2048; i += 256) {
            int kk = i >> 7, n = i & 127;
            int gn = bn + n;
            Ws[kk][n] = (gn < N) ? W[(size_t)(k0 + kk) * N + gn] : 0.f;
        }
        __syncthreads();
#pragma unroll
        for (int kk = 0; kk < 16; kk++) {
            float4 a0 = *reinterpret_cast<const float4*>(&As[kk][tm * 8]);
            float4 a1 = *reinterpret_cast<const float4*>(&As[kk][tm * 8 + 4]);
            float4 w0 = *reinterpret_cast<const float4*>(&Ws[kk][tn * 8]);
            float4 w1 = *reinterpret_cast<const float4*>(&Ws[kk][tn * 8 + 4]);
            float a[8] = {a0.x, a0.y, a0.z, a0.w, a1.x, a1.y, a1.z, a1.w};
            float w[8] = {w0.x, w0.y, w0.z, w0.w, w1.x, w1.y, w1.z, w1.w};
#pragma unroll
            for (int x = 0; x < 8; x++)
#pragma unroll
                for (int y = 0; y < 8; y++) acc[x][y] = fmaf(a[x], w[y], acc[x][y]);
        }
        __syncthreads();
    }

#pragma unroll
    for (int x = 0; x < 8; x++) {
        int gm = bm + tm * 8 + x;
#pragma unroll
        for (int y = 0; y < 8; y++) {
            int gn = bn + tn * 8 + y;
            if (gn < N) {
                float vv = acc[x][y] + bias[gn];
                if (act) vv = gelu_exact(vv);
                C[(size_t)gm * N + gn] = vv;
            }
        }
    }
}

// ---------------------------------------------------------------------------
// Flash attention: 64q x 64k tiles, dh=32, online softmax (R2-proven).
// ---------------------------------------------------------------------------
__global__ __launch_bounds__(256) void attn_k(
    const float* __restrict__ Q, const float* __restrict__ K,
    const float* __restrict__ V, float* __restrict__ O, int mode)
{
    const int E = EMB;
    int bh = blockIdx.y;
    size_t base = (size_t)(bh >> 2) * T_SEQ * E + (size_t)(bh & 3) * DHEAD;
    int q0 = (gridDim.x - 1 - blockIdx.x) * 64;

    __shared__ float Ks[64 * 32];
    __shared__ float Vs[64 * 32];

    const int tid = threadIdx.x;
    const int rp = tid >> 3;
    const int g  = tid & 7;
    const int i0 = q0 + rp * 2;
    const int i1 = i0 + 1;

    float q0r[32], q1r[32];
#pragma unroll
    for (int d4 = 0; d4 < 8; d4++) {
        float4 a = *reinterpret_cast<const float4*>(&Q[base + (size_t)i0 * E + d4 * 4]);
        float4 b = *reinterpret_cast<const float4*>(&Q[base + (size_t)i1 * E + d4 * 4]);
        q0r[d4*4+0] = a.x; q0r[d4*4+1] = a.y; q0r[d4*4+2] = a.z; q0r[d4*4+3] = a.w;
        q1r[d4*4+0] = b.x; q1r[d4*4+1] = b.y; q1r[d4*4+2] = b.z; q1r[d4*4+3] = b.w;
    }

    const float NEGINF = __int_as_float(0xff800000);
    float m0 = NEGINF, m1 = NEGINF, l0 = 0.f, l1 = 0.f;
    float o0[32], o1[32];
#pragma unroll
    for (int d = 0; d < 32; d++) { o0[d] = 0.f; o1[d] = 0.f; }

    for (int j0 = 0; j0 <= q0; j0 += 64) {
        __syncthreads();
#pragma unroll
        for (int i = tid; i < 512; i += 256) {
            int n = i >> 3, d4 = i & 7;
            int pq = (d4 ^ (n >> 3)) << 2;
            float4 kk = *reinterpret_cast<const float4*>(&K[base + (size_t)(j0 + n) * E + d4 * 4]);
            float4 vv = *reinterpret_cast<const float4*>(&V[base + (size_t)(j0 + n) * E + d4 * 4]);
            *reinterpret_cast<float4*>(&Ks[n * 32 + pq]) = kk;
            *reinterpret_cast<float4*>(&Vs[n * 32 + pq]) = vv;
        }
        __syncthreads();

        float s0[8], s1[8];
        float ml0 = NEGINF, ml1 = NEGINF;
#pragma unroll
        for (int c = 0; c < 8; c++) {
            int kr = g * 8 + c;
            const float* krow = &Ks[kr * 32];
            float a0 = 0.f, a1 = 0.f;
#pragma unroll
            for (int d4 = 0; d4 < 8; d4++) {
                float4 kk = *reinterpret_cast<const float4*>(&krow[(d4 ^ g) << 2]);
                a0 = fmaf(q0r[d4*4+0], kk.x, a0); a1 = fmaf(q1r[d4*4+0], kk.x, a1);
                a0 = fmaf(q0r[d4*4+1], kk.y, a0); a1 = fmaf(q1r[d4*4+1], kk.y, a1);
                a0 = fmaf(q0r[d4*4+2], kk.z, a0); a1 = fmaf(q1r[d4*4+2], kk.z, a1);
                a0 = fmaf(q0r[d4*4+3], kk.w, a0); a1 = fmaf(q1r[d4*4+3], kk.w, a1);
            }
            int j = j0 + kr;
            bool ok0 = (mode == 0) ? (j <= i0) : ((j < i0) || (i0 == 0 && j == 0));
            bool ok1 = (mode == 0) ? (j <= i1) : (j < i1);
            s0[c] = ok0 ? a0 : NEGINF;
            s1[c] = ok1 ? a1 : NEGINF;
            ml0 = fmaxf(ml0, s0[c]);
            ml1 = fmaxf(ml1, s1[c]);
        }
        ml0 = fmaxf(ml0, __shfl_xor_sync(0xffffffffu, ml0, 1));
        ml0 = fmaxf(ml0, __shfl_xor_sync(0xffffffffu, ml0, 2));
        ml0 = fmaxf(ml0, __shfl_xor_sync(0xffffffffu, ml0, 4));
        ml1 = fmaxf(ml1, __shfl_xor_sync(0xffffffffu, ml1, 1));
        ml1 = fmaxf(ml1, __shfl_xor_sync(0xffffffffu, ml1, 2));
        ml1 = fmaxf(ml1, __shfl_xor_sync(0xffffffffu, ml1, 4));

        float mn0 = fmaxf(m0, ml0);
        float mn1 = fmaxf(m1, ml1);
        float sc0 = __expf(m0 - mn0);
        float sc1 = __expf(m1 - mn1);

        float ll0 = 0.f, ll1 = 0.f;
#pragma unroll
        for (int c = 0; c < 8; c++) {
            s0[c] = __expf(s0[c] - mn0);
            s1[c] = __expf(s1[c] - mn1);
            ll0 += s0[c]; ll1 += s1[c];
        }
        l0 = l0 * sc0 + ll0;
        l1 = l1 * sc1 + ll1;
#pragma unroll
        for (int d = 0; d < 32; d++) { o0[d] *= sc0; o1[d] *= sc1; }

#pragma unroll
        for (int c = 0; c < 8; c++) {
            int kr = g * 8 + c;
            const float* vrow = &Vs[kr * 32];
            float p0 = s0[c], p1 = s1[c];
#pragma unroll
            for (int d4 = 0; d4 < 8; d4++) {
                float4 vv = *reinterpret_cast<const float4*>(&vrow[(d4 ^ g) << 2]);
                o0[d4*4+0] = fmaf(p0, vv.x, o0[d4*4+0]); o1[d4*4+0] = fmaf(p1, vv.x, o1[d4*4+0]);
                o0[d4*4+1] = fmaf(p0, vv.y, o0[d4*4+1]); o1[d4*4+1] = fmaf(p1, vv.y, o1[d4*4+1]);
                o0[d4*4+2] = fmaf(p0, vv.z, o0[d4*4+2]); o1[d4*4+2] = fmaf(p1, vv.z, o1[d4*4+2]);
                o0[d4*4+3] = fmaf(p0, vv.w, o0[d4*4+3]); o1[d4*4+3] = fmaf(p1, vv.w, o1[d4*4+3]);
            }
        }
        m0 = mn0; m1 = mn1;
    }

    l0 += __shfl_xor_sync(0xffffffffu, l0, 1);
    l0 += __shfl_xor_sync(0xffffffffu, l0, 2);
    l0 += __shfl_xor_sync(0xffffffffu, l0, 4);
    l1 += __shfl_xor_sync(0xffffffffu, l1, 1);
    l1 += __shfl_xor_sync(0xffffffffu, l1, 2);
    l1 += __shfl_xor_sync(0xffffffffu, l1, 4);
    float inv0 = 1.f / l0;
    float inv1 = 1.f / l1;
#pragma unroll
    for (int d = 0; d < 32; d++) {
        o0[d] += __shfl_xor_sync(0xffffffffu, o0[d], 1);
        o0[d] += __shfl_xor_sync(0xffffffffu, o0[d], 2);
        o0[d] += __shfl_xor_sync(0xffffffffu, o0[d], 4);
        o1[d] += __shfl_xor_sync(0xffffffffu, o1[d], 1);
        o1[d] += __shfl_xor_sync(0xffffffffu, o1[d], 2);
        o1[d] += __shfl_xor_sync(0xffffffffu, o1[d], 4);
    }
    float4 w0, w1;
    w0.x = o0[g*4+0] * inv0; w0.y = o0[g*4+1] * inv0; w0.z = o0[g*4+2] * inv0; w0.w = o0[g*4+3] * inv0;
    w1.x = o1[g*4+0] * inv1; w1.y = o1[g*4+1] * inv1; w1.z = o1[g*4+2] * inv1; w1.w = o1[g*4+3] * inv1;
    *reinterpret_cast<float4*>(&O[base + (size_t)i0 * E + g * 4]) = w0;
    *reinterpret_cast<float4*>(&O[base + (size_t)i1 * E + g * 4]) = w1;
}

// ---------------------------------------------------------------------------
// out = LayerNorm(A + B) * gamma + beta, row dim 128, eps 1e-5
// ---------------------------------------------------------------------------
__global__ void add_ln_k(const float* __restrict__ A, const float* __restrict__ Bv,
                         const float* __restrict__ gam, const float* __restrict__ bet,
                         float* __restrict__ out)
{
    int row = blockIdx.x;
    int d = threadIdx.x;  // 128
    float x = A[(size_t)row * 128 + d] + Bv[(size_t)row * 128 + d];

    __shared__ float ws[4], ws2[4];
    float v = x;
#pragma unroll
    for (int off = 16; off; off >>= 1) v += __shfl_xor_sync(0xffffffffu, v, off);
    if ((d & 31) == 0) ws[d >> 5] = v;
    __syncthreads();
    float mean = (ws[0] + ws[1] + ws[2] + ws[3]) * (1.f / 128.f);
    float dif = x - mean;
    float v2 = dif * dif;
#pragma unroll
    for (int off = 16; off; off >>= 1) v2 += __shfl_xor_sync(0xffffffffu, v2, off);
    if ((d & 31) == 0) ws2[d >> 5] = v2;
    __syncthreads();
    float var = (ws2[0] + ws2[1] + ws2[2] + ws2[3]) * (1.f / 128.f);
    out[(size_t)row * 128 + d] = dif * rsqrtf(var + 1e-5f) * gam[d] + bet[d];
}

// ---------------------------------------------------------------------------
extern "C" void kernel_launch(void* const* d_in, const int* in_sizes, int n_in,
                              void* d_out, int out_size)
{
    const float* kq    = (const float*)d_in[0];
    const float* v_in  = (const float*)d_in[1];
    const float* A_Wk  = (const float*)d_in[2];
    const float* A_bk  = (const float*)d_in[3];
    const float* A_Wq  = (const float*)d_in[4];
    const float* A_bq  = (const float*)d_in[5];
    const float* A_Wv  = (const float*)d_in[6];
    const float* A_bv  = (const float*)d_in[7];
    const float* A_f1W = (const float*)d_in[8];
    const float* A_f1b = (const float*)d_in[9];
    const float* A_f2W = (const float*)d_in[10];
    const float* A_f2b = (const float*)d_in[11];
    const float* A_n1g = (const float*)d_in[12];
    const float* A_n1b = (const float*)d_in[13];
    const float* A_n2g = (const float*)d_in[14];
    const float* A_n2b = (const float*)d_in[15];
    const float* B_Wk  = (const float*)d_in[16];
    const float* B_bk  = (const float*)d_in[17];
    const float* B_Wq  = (const float*)d_in[18];
    const float* B_bq  = (const float*)d_in[19];
    const float* B_Wv  = (const float*)d_in[20];
    const float* B_bv  = (const float*)d_in[21];
    const float* B_f1W = (const float*)d_in[22];
    const float* B_f1b = (const float*)d_in[23];
    const float* B_f2W = (const float*)d_in[24];
    const float* B_f2b = (const float*)d_in[25];
    const float* out_W = (const float*)d_in[26];
    const float* out_b = (const float*)d_in[27];
    float* out = (float*)d_out;

    float* pool = nullptr;
    cudaGetSymbolAddress((void**)&pool, g_scratch);

    const size_t S128 = (size_t)R_TOTAL * 128;  // 2M floats
    float* Ka    = pool + 1 * S128;
    float* Qa    = pool + 2 * S128;
    float* Va    = pool + 3 * S128;
    float* attnA = pool + 4 * S128;
    float* h1    = pool + 5 * S128;
    float* t1    = pool + 6 * S128;
    float* vA    = pool + 7 * S128;
    float* K2    = pool + 8 * S128;
    float* Q2    = pool + 9 * S128;
    float* V2    = pool + 10 * S128;
    float* attn2 = pool + 11 * S128;
    float* ffb   = pool + 12 * S128;
    float* ff    = pool + 13 * S128;  // R x 512 fp32 (slots 13..16)

    // bf16 regions
    __nv_bfloat16* sAh = (__nv_bfloat16*)(pool + 17 * S128);   // 8M bf16 capacity
    __nv_bfloat16* sAl = (__nv_bfloat16*)(pool + 19 * S128);
    __nv_bfloat16* wb  = (__nv_bfloat16*)(pool + 21 * S128);
    __nv_bfloat16* aWk_h = wb;            __nv_bfloat16* aWk_l = wb + 16384;
    __nv_bfloat16* aWq_h = wb + 32768;    __nv_bfloat16* aWq_l = wb + 49152;
    __nv_bfloat16* aWv_h = wb + 65536;    __nv_bfloat16* aWv_l = wb + 81920;
    __nv_bfloat16* af1_h = wb + 98304;    __nv_bfloat16* af1_l = af1_h + 65536;   // Wt[512][128]
    __nv_bfloat16* af2_h = af1_l + 65536; __nv_bfloat16* af2_l = af2_h + 65536;   // Wt[128][512]
    __nv_bfloat16* bWk_h = af2_l + 65536; __nv_bfloat16* bWk_l = bWk_h + 8192;    // Wt[128][64]
    __nv_bfloat16* bWq_h = bWk_l + 8192;  __nv_bfloat16* bWq_l = bWq_h + 8192;
    __nv_bfloat16* bWv_h = bWq_l + 8192;  __nv_bfloat16* bWv_l = bWv_h + 16384;   // Wt[128][128]
    __nv_bfloat16* bf1_h = bWv_l + 16384; __nv_bfloat16* bf1_l = bf1_h + 65536;
    __nv_bfloat16* bf2_h = bf1_l + 65536; __nv_bfloat16* bf2_l = bf2_h + 65536;

    dim3 blk256(256);
    dim3 gN128(1, R_TOTAL / 128);
    dim3 gN512(4, R_TOTAL / 128);
    dim3 attnGrid(T_SEQ / 64, 8 * NHEAD);

    // ---- weight transforms ----
    tsplit_k<<<(128*128+255)/256, 256>>>(A_Wk, aWk_h, aWk_l, 128, 128);
    tsplit_k<<<(128*128+255)/256, 256>>>(A_Wq, aWq_h, aWq_l, 128, 128);
    tsplit_k<<<(128*128+255)/256, 256>>>(A_Wv, aWv_h, aWv_l, 128, 128);
    tsplit_k<<<(128*512+255)/256, 256>>>(A_f1W, af1_h, af1_l, 128, 512);
    tsplit_k<<<(512*128+255)/256, 256>>>(A_f2W, af2_h, af2_l, 512, 128);
    tsplit_k<<<(64*128+255)/256, 256>>>(B_Wk, bWk_h, bWk_l, 64, 128);
    tsplit_k<<<(64*128+255)/256, 256>>>(B_Wq, bWq_h, bWq_l, 64, 128);
    tsplit_k<<<(128*128+255)/256, 256>>>(B_Wv, bWv_h, bWv_l, 128, 128);
    tsplit_k<<<(128*512+255)/256, 256>>>(B_f1W, bf1_h, bf1_l, 128, 512);
    tsplit_k<<<(512*128+255)/256, 256>>>(B_f2W, bf2_h, bf2_l, 512, 128);

    // ---- Layer A ----
    splitcat_k<<<(R_TOTAL*32+255)/256, 256>>>(kq, v_in, sAh, sAl);
    mma_gemm<<<gN128, blk256>>>(sAh, sAl, aWk_h, aWk_l, A_bk, Ka, 128, 128, 0);
    mma_gemm<<<gN128, blk256>>>(sAh, sAl, aWq_h, aWq_l, A_bq, Qa, 128, 128, 0);
    mma_gemm<<<gN128, blk256>>>(sAh, sAl, aWv_h, aWv_l, A_bv, Va, 128, 128, 0);
    attn_k<<<attnGrid, blk256>>>(Qa, Ka, Va, attnA, 0);
    add_ln_k<<<R_TOTAL, 128>>>(Va, attnA, A_n1g, A_n1b, h1);
    split_k<<<(2*1024*1024/4+255)/256, 256>>>(h1, sAh, sAl, 2*1024*1024/4);
    mma_gemm<<<gN512, blk256>>>(sAh, sAl, af1_h, af1_l, A_f1b, ff, 128, 512, 1);
    split_k<<<(8*1024*1024/4+255)/256, 256>>>(ff, sAh, sAl, 8*1024*1024/4);
    mma_gemm<<<gN128, blk256>>>(sAh, sAl, af2_h, af2_l, A_f2b, t1, 512, 128, 0);
    add_ln_k<<<R_TOTAL, 128>>>(h1, t1, A_n2g, A_n2b, vA);

    // ---- Layer B ----
    split_k<<<(1024*1024/4+255)/256, 256>>>(kq, sAh, sAl, 1024*1024/4);
    mma_gemm<<<gN128, blk256>>>(sAh, sAl, bWk_h, bWk_l, B_bk, K2, 64, 128, 0);
    mma_gemm<<<gN128, blk256>>>(sAh, sAl, bWq_h, bWq_l, B_bq, Q2, 64, 128, 0);
    split_k<<<(2*1024*1024/4+255)/256, 256>>>(vA, sAh, sAl, 2*1024*1024/4);
    mma_gemm<<<gN128, blk256>>>(sAh, sAl, bWv_h, bWv_l, B_bv, V2, 128, 128, 0);
    attn_k<<<attnGrid, blk256>>>(Q2, K2, V2, attn2, 1);
    split_k<<<(2*1024*1024/4+255)/256, 256>>>(attn2, sAh, sAl, 2*1024*1024/4);
    mma_gemm<<<gN512, blk256>>>(sAh, sAl, bf1_h, bf1_l, B_f1b, ff, 128, 512, 1);
    split_k<<<(8*1024*1024/4+255)/256, 256>>>(ff, sAh, sAl, 8*1024*1024/4);
    mma_gemm<<<gN128, blk256>>>(sAh, sAl, bf2_h, bf2_l, B_f2b, ffb, 512, 128, 0);

    // ---- OUT head (fp32, N=32) ----
    sgemm_k<<<dim3(1, R_TOTAL / 128), blk256>>>(ffb, out_W, out_b, out, R_TOTAL, 32, 128, 0);
}

// round 6
// speedup vs baseline: 6.0143x; 2.0119x over previous
#include <cuda_runtime.h>
#include <cuda_bf16.h>
#include <math.h>
#include <stdint.h>

// ---------------------------------------------------------------------------
// Model_19104014532987: 2-layer transformer
// B=8 T=2048 DKQ=64 DV=64 EKQ=EV=128 H=4 dh=32 FF=512 OUT=32, R=16384
// GEMMs + attention on mma.sync bf16 (HMMA), bf16x3 split precision.
// ---------------------------------------------------------------------------

#define R_TOTAL 16384
#define T_SEQ   2048
#define EMB     128
#define NHEAD   4
#define LOG2E   1.4426950408889634f

// Scratch pool: 56M floats (224 MB), static device allocation (allowed).
static __device__ __align__(256) float g_scratch[56ull * 1024 * 1024];

__device__ __forceinline__ float gelu_exact(float x) {
    return 0.5f * x * (1.0f + erff(x * 0.70710678118654752440f));
}
__device__ __forceinline__ float ex2(float x) {
    float y; asm("ex2.approx.ftz.f32 %0, %1;" : "=f"(y) : "f"(x)); return y;
}
__device__ __forceinline__ uint32_t smem_u32(const void* p) {
    uint32_t a;
    asm("{ .reg .u64 t; cvta.to.shared.u64 t, %1; cvt.u32.u64 %0, t; }" : "=r"(a) : "l"(p));
    return a;
}

#define LDMX4(r0, r1, r2, r3, addr) \
    asm volatile("ldmatrix.sync.aligned.m8n8.x4.shared.b16 {%0,%1,%2,%3}, [%4];" \
        : "=r"(r0), "=r"(r1), "=r"(r2), "=r"(r3) : "r"(addr))
#define LDMX4T(r0, r1, r2, r3, addr) \
    asm volatile("ldmatrix.sync.aligned.m8n8.x4.trans.shared.b16 {%0,%1,%2,%3}, [%4];" \
        : "=r"(r0), "=r"(r1), "=r"(r2), "=r"(r3) : "r"(addr))
#define MMA16816(d, a, b0, b1) \
    asm volatile("mma.sync.aligned.m16n8k16.row.col.f32.bf16.bf16.f32 " \
        "{%0,%1,%2,%3}, {%4,%5,%6,%7}, {%8,%9}, {%0,%1,%2,%3};" \
        : "+f"((d)[0]), "+f"((d)[1]), "+f"((d)[2]), "+f"((d)[3]) \
        : "r"((a)[0]), "r"((a)[1]), "r"((a)[2]), "r"((a)[3]), "r"(b0), "r"(b1))

__device__ __forceinline__ void packpair(uint32_t& ph, uint32_t& pl, float x, float y) {
    __nv_bfloat16 hx = __float2bfloat16(x), hy = __float2bfloat16(y);
    __nv_bfloat162 t; t.x = hx; t.y = hy;
    ph = *reinterpret_cast<uint32_t*>(&t);
    __nv_bfloat162 u;
    u.x = __float2bfloat16(x - __bfloat162float(hx));
    u.y = __float2bfloat16(y - __bfloat162float(hy));
    pl = *reinterpret_cast<uint32_t*>(&u);
}

// ---------------------------------------------------------------------------
// split: fp32 -> bf16 hi + lo
// ---------------------------------------------------------------------------
__global__ void split_k(const float* __restrict__ x, __nv_bfloat16* __restrict__ h,
                        __nv_bfloat16* __restrict__ l, int n4) {
    int i = blockIdx.x * 256 + threadIdx.x;
    if (i >= n4) return;
    float4 v = reinterpret_cast<const float4*>(x)[i];
    uint32_t h01, l01, h23, l23;
    packpair(h01, l01, v.x, v.y);
    packpair(h23, l23, v.z, v.w);
    reinterpret_cast<uint32_t*>(h)[i * 2]     = h01;
    reinterpret_cast<uint32_t*>(h)[i * 2 + 1] = h23;
    reinterpret_cast<uint32_t*>(l)[i * 2]     = l01;
    reinterpret_cast<uint32_t*>(l)[i * 2 + 1] = l23;
}

// splitcat: X = [kq | v] -> bf16 hi/lo directly
__global__ void splitcat_k(const float* __restrict__ kq, const float* __restrict__ v,
                           __nv_bfloat16* __restrict__ h, __nv_bfloat16* __restrict__ l) {
    int i = blockIdx.x * 256 + threadIdx.x;
    if (i >= R_TOTAL * 32) return;
    int e = i * 4;
    int r = e >> 7, d = e & 127;
    float4 val = (d < 64)
        ? *reinterpret_cast<const float4*>(&kq[(size_t)r * 64 + d])
        : *reinterpret_cast<const float4*>(&v[(size_t)r * 64 + (d - 64)]);
    uint32_t h01, l01, h23, l23;
    packpair(h01, l01, val.x, val.y);
    packpair(h23, l23, val.z, val.w);
    reinterpret_cast<uint32_t*>(h)[i * 2]     = h01;
    reinterpret_cast<uint32_t*>(h)[i * 2 + 1] = h23;
    reinterpret_cast<uint32_t*>(l)[i * 2]     = l01;
    reinterpret_cast<uint32_t*>(l)[i * 2 + 1] = l23;
}

// transpose+split: W[K,N] -> Wt[N,K] bf16 hi/lo
__global__ void tsplit_k(const float* __restrict__ W, __nv_bfloat16* __restrict__ th,
                         __nv_bfloat16* __restrict__ tl, int Kd, int Nd) {
    int idx = blockIdx.x * 256 + threadIdx.x;
    if (idx >= Kd * Nd) return;
    int n = idx / Kd, k = idx - n * Kd;
    float w = W[(size_t)k * Nd + n];
    __nv_bfloat16 h = __float2bfloat16(w);
    th[idx] = h;
    tl[idx] = __float2bfloat16(w - __bfloat162float(h));
}

// ---------------------------------------------------------------------------
// mma_gemm: 128x128 tile, bf16x3 split. Optional fp32 out (Cf) and/or
// bf16 hi/lo out (Ch/Cl). oscale applied to (acc+bias) before act.
// ---------------------------------------------------------------------------
__global__ __launch_bounds__(256) void mma_gemm(
    const __nv_bfloat16* __restrict__ Ah, const __nv_bfloat16* __restrict__ Al,
    const __nv_bfloat16* __restrict__ Bh, const __nv_bfloat16* __restrict__ Bl,
    const float* __restrict__ bias, float* __restrict__ Cf,
    __nv_bfloat16* __restrict__ Ch, __nv_bfloat16* __restrict__ Cl,
    int K, int Nstride, int act, float oscale)
{
    __shared__ __align__(16) __nv_bfloat16 smAh[128 * 40];
    __shared__ __align__(16) __nv_bfloat16 smAl[128 * 40];
    __shared__ __align__(16) __nv_bfloat16 smBh[128 * 40];
    __shared__ __align__(16) __nv_bfloat16 smBl[128 * 40];

    const int tid = threadIdx.x;
    const int l = tid & 31, w = tid >> 5;
    const int wm = w >> 1, wn = w & 1;
    const int bm = blockIdx.y * 128, bn = blockIdx.x * 128;

    float d[2][8][4];
#pragma unroll
    for (int mt = 0; mt < 2; mt++)
#pragma unroll
        for (int nt = 0; nt < 8; nt++)
#pragma unroll
            for (int q = 0; q < 4; q++) d[mt][nt][q] = 0.f;

    const uint32_t aAh = smem_u32(smAh), aAl = smem_u32(smAl);
    const uint32_t aBh = smem_u32(smBh), aBl = smem_u32(smBl);

    const int a_row = wm * 32 + (l & 7) + ((l >> 3) & 1) * 8;
    const int a_kof = (l >> 4) * 8;
    const int b_row = wn * 64 + (l >> 4) * 8 + (l & 7);
    const int b_kof = ((l >> 3) & 1) * 8;

    for (int kc = 0; kc < K; kc += 32) {
        if (kc) __syncthreads();
#pragma unroll
        for (int i = tid; i < 512; i += 256) {
            int row = i >> 2, ch = i & 3;
            size_t ga = (size_t)(bm + row) * K + kc + ch * 8;
            size_t gb = (size_t)(bn + row) * K + kc + ch * 8;
            int sa = row * 40 + ch * 8;
            *reinterpret_cast<uint4*>(smAh + sa) = *reinterpret_cast<const uint4*>(Ah + ga);
            *reinterpret_cast<uint4*>(smAl + sa) = *reinterpret_cast<const uint4*>(Al + ga);
            *reinterpret_cast<uint4*>(smBh + sa) = *reinterpret_cast<const uint4*>(Bh + gb);
            *reinterpret_cast<uint4*>(smBl + sa) = *reinterpret_cast<const uint4*>(Bl + gb);
        }
        __syncthreads();

#pragma unroll
        for (int ks = 0; ks < 32; ks += 16) {
            uint32_t ah[2][4], al2[2][4];
#pragma unroll
            for (int mt = 0; mt < 2; mt++) {
                uint32_t off = (uint32_t)(((a_row + mt * 16) * 40 + a_kof + ks) * 2);
                LDMX4(ah[mt][0], ah[mt][1], ah[mt][2], ah[mt][3], aAh + off);
                LDMX4(al2[mt][0], al2[mt][1], al2[mt][2], al2[mt][3], aAl + off);
            }
#pragma unroll
            for (int j = 0; j < 4; j++) {
                uint32_t boff = (uint32_t)(((b_row + j * 16) * 40 + b_kof + ks) * 2);
                uint32_t bh[4], bl2[4];
                LDMX4(bh[0], bh[1], bh[2], bh[3], aBh + boff);
                LDMX4(bl2[0], bl2[1], bl2[2], bl2[3], aBl + boff);
#pragma unroll
                for (int mt = 0; mt < 2; mt++) {
                    MMA16816(d[mt][2 * j],     ah[mt],  bh[0],  bh[1]);
                    MMA16816(d[mt][2 * j],     al2[mt], bh[0],  bh[1]);
                    MMA16816(d[mt][2 * j],     ah[mt],  bl2[0], bl2[1]);
                    MMA16816(d[mt][2 * j + 1], ah[mt],  bh[2],  bh[3]);
                    MMA16816(d[mt][2 * j + 1], al2[mt], bh[2],  bh[3]);
                    MMA16816(d[mt][2 * j + 1], ah[mt],  bl2[2], bl2[3]);
                }
            }
        }
    }

#pragma unroll
    for (int mt = 0; mt < 2; mt++) {
        int r0 = bm + wm * 32 + mt * 16 + (l >> 2);
#pragma unroll
        for (int nt = 0; nt < 8; nt++) {
            int c = bn + wn * 64 + nt * 8 + (l & 3) * 2;
            float b0 = bias[c], b1 = bias[c + 1];
            float2 v0, v1;
            v0.x = (d[mt][nt][0] + b0) * oscale; v0.y = (d[mt][nt][1] + b1) * oscale;
            v1.x = (d[mt][nt][2] + b0) * oscale; v1.y = (d[mt][nt][3] + b1) * oscale;
            if (act) {
                v0.x = gelu_exact(v0.x); v0.y = gelu_exact(v0.y);
                v1.x = gelu_exact(v1.x); v1.y = gelu_exact(v1.y);
            }
            if (Cf) {
                *reinterpret_cast<float2*>(&Cf[(size_t)r0 * Nstride + c]) = v0;
                *reinterpret_cast<float2*>(&Cf[(size_t)(r0 + 8) * Nstride + c]) = v1;
            }
            if (Ch) {
                uint32_t h0, l0p, h1v, l1p;
                packpair(h0, l0p, v0.x, v0.y);
                packpair(h1v, l1p, v1.x, v1.y);
                *reinterpret_cast<uint32_t*>(&Ch[(size_t)r0 * Nstride + c]) = h0;
                *reinterpret_cast<uint32_t*>(&Cl[(size_t)r0 * Nstride + c]) = l0p;
                *reinterpret_cast<uint32_t*>(&Ch[(size_t)(r0 + 8) * Nstride + c]) = h1v;
                *reinterpret_cast<uint32_t*>(&Cl[(size_t)(r0 + 8) * Nstride + c]) = l1p;
            }
        }
    }
}

// ---------------------------------------------------------------------------
// attn_tc: tensor-core flash attention. bf16 hi/lo Q,K,V in [B,T,128] layout,
// head h at cols h*32. Q pre-scaled by log2(e) -> softmax uses ex2.
// 128 threads = 4 warps x 16 q rows. 64q x 64k tiles, dh=32.
// Outputs fp32 (Of) and/or bf16 hi/lo (Oh/Ol).
// mode 0: j <= i.  mode 1: j < i OR (i==0 && j==0).
// ---------------------------------------------------------------------------
__global__ __launch_bounds__(128) void attn_tc(
    const __nv_bfloat16* __restrict__ Qh, const __nv_bfloat16* __restrict__ Ql,
    const __nv_bfloat16* __restrict__ Kh, const __nv_bfloat16* __restrict__ Kl,
    const __nv_bfloat16* __restrict__ Vh, const __nv_bfloat16* __restrict__ Vl,
    float* __restrict__ Of, __nv_bfloat16* __restrict__ Oh, __nv_bfloat16* __restrict__ Ol,
    int mode)
{
    __shared__ __align__(16) __nv_bfloat16 sQh[64 * 40], sQl[64 * 40];
    __shared__ __align__(16) __nv_bfloat16 sKh[64 * 40], sKl[64 * 40];
    __shared__ __align__(16) __nv_bfloat16 sVh[64 * 40], sVl[64 * 40];

    const int tid = threadIdx.x, l = tid & 31, w = tid >> 5;
    const int bh = blockIdx.y;
    const size_t base = (size_t)(bh >> 2) * T_SEQ * EMB + (size_t)(bh & 3) * 32;
    const int q0 = (gridDim.x - 1 - blockIdx.x) * 64;

    // Q tile -> smem, then fragments
    for (int i = tid; i < 256; i += 128) {
        int row = i >> 2, ch = i & 3;
        size_t g = base + (size_t)(q0 + row) * EMB + ch * 8;
        *reinterpret_cast<uint4*>(&sQh[row * 40 + ch * 8]) = *reinterpret_cast<const uint4*>(&Qh[g]);
        *reinterpret_cast<uint4*>(&sQl[row * 40 + ch * 8]) = *reinterpret_cast<const uint4*>(&Ql[g]);
    }
    __syncthreads();

    const uint32_t aQh = smem_u32(sQh), aQl = smem_u32(sQl);
    const uint32_t aKh = smem_u32(sKh), aKl = smem_u32(sKl);
    const uint32_t aVh = smem_u32(sVh), aVl = smem_u32(sVl);

    uint32_t qh[2][4], ql[2][4];
    const int a_row = w * 16 + (l & 7) + ((l >> 3) & 1) * 8;
    const int a_col = (l >> 4) * 8;
#pragma unroll
    for (int ks = 0; ks < 2; ks++) {
        uint32_t off = (uint32_t)((a_row * 40 + a_col + ks * 16) * 2);
        LDMX4(qh[ks][0], qh[ks][1], qh[ks][2], qh[ks][3], aQh + off);
        LDMX4(ql[ks][0], ql[ks][1], ql[ks][2], ql[ks][3], aQl + off);
    }

    const float NEG = -1e30f;
    const int r0 = q0 + w * 16 + (l >> 2);
    const int r1 = r0 + 8;
    float m0 = NEG, m1 = NEG, lac0 = 0.f, lac1 = 0.f;
    float o[4][4];
#pragma unroll
    for (int n = 0; n < 4; n++)
#pragma unroll
        for (int q = 0; q < 4; q++) o[n][q] = 0.f;

    const int b_row_base = (l >> 4) * 8 + (l & 7);
    const int b_kof = ((l >> 3) & 1) * 8;

    for (int j0 = 0; j0 <= q0; j0 += 64) {
        __syncthreads();
        for (int i = tid; i < 256; i += 128) {
            int row = i >> 2, ch = i & 3;
            size_t g = base + (size_t)(j0 + row) * EMB + ch * 8;
            *reinterpret_cast<uint4*>(&sKh[row * 40 + ch * 8]) = *reinterpret_cast<const uint4*>(&Kh[g]);
            *reinterpret_cast<uint4*>(&sKl[row * 40 + ch * 8]) = *reinterpret_cast<const uint4*>(&Kl[g]);
            *reinterpret_cast<uint4*>(&sVh[row * 40 + ch * 8]) = *reinterpret_cast<const uint4*>(&Vh[g]);
            *reinterpret_cast<uint4*>(&sVl[row * 40 + ch * 8]) = *reinterpret_cast<const uint4*>(&Vl[g]);
        }
        __syncthreads();

        // ---- S = Q K^T (bf16x3) ----
        float s[8][4];
#pragma unroll
        for (int nt = 0; nt < 8; nt++)
#pragma unroll
            for (int q = 0; q < 4; q++) s[nt][q] = 0.f;

#pragma unroll
        for (int ks = 0; ks < 2; ks++) {
#pragma unroll
            for (int jp = 0; jp < 4; jp++) {
                uint32_t off = (uint32_t)(((jp * 16 + b_row_base) * 40 + b_kof + ks * 16) * 2);
                uint32_t kb[4], kbl[4];
                LDMX4(kb[0], kb[1], kb[2], kb[3], aKh + off);
                LDMX4(kbl[0], kbl[1], kbl[2], kbl[3], aKl + off);
                MMA16816(s[2 * jp],     qh[ks], kb[0],  kb[1]);
                MMA16816(s[2 * jp],     ql[ks], kb[0],  kb[1]);
                MMA16816(s[2 * jp],     qh[ks], kbl[0], kbl[1]);
                MMA16816(s[2 * jp + 1], qh[ks], kb[2],  kb[3]);
                MMA16816(s[2 * jp + 1], ql[ks], kb[2],  kb[3]);
                MMA16816(s[2 * jp + 1], qh[ks], kbl[2], kbl[3]);
            }
        }

        // ---- mask (diagonal tile only) ----
        if (j0 >= q0) {
#pragma unroll
            for (int nt = 0; nt < 8; nt++) {
                int cb = j0 + nt * 8 + (l & 3) * 2;
                if (mode == 0) {
                    if (cb     > r0) s[nt][0] = NEG;
                    if (cb + 1 > r0) s[nt][1] = NEG;
                    if (cb     > r1) s[nt][2] = NEG;
                    if (cb + 1 > r1) s[nt][3] = NEG;
                } else {
                    if (!(cb     < r0 || (r0 == 0 && cb == 0))) s[nt][0] = NEG;
                    if (!(cb + 1 < r0))                          s[nt][1] = NEG;
                    if (!(cb     < r1)) s[nt][2] = NEG;
                    if (!(cb + 1 < r1)) s[nt][3] = NEG;
                }
            }
        }

        // ---- online softmax ----
        float ml0 = NEG, ml1 = NEG;
#pragma unroll
        for (int nt = 0; nt < 8; nt++) {
            ml0 = fmaxf(ml0, fmaxf(s[nt][0], s[nt][1]));
            ml1 = fmaxf(ml1, fmaxf(s[nt][2], s[nt][3]));
        }
        ml0 = fmaxf(ml0, __shfl_xor_sync(0xffffffffu, ml0, 1));
        ml0 = fmaxf(ml0, __shfl_xor_sync(0xffffffffu, ml0, 2));
        ml1 = fmaxf(ml1, __shfl_xor_sync(0xffffffffu, ml1, 1));
        ml1 = fmaxf(ml1, __shfl_xor_sync(0xffffffffu, ml1, 2));
        float mn0 = fmaxf(m0, ml0), mn1 = fmaxf(m1, ml1);
        float sc0 = ex2(m0 - mn0), sc1 = ex2(m1 - mn1);

        uint32_t pah[4][4], pal[4][4];
        float ps0 = 0.f, ps1 = 0.f;
#pragma unroll
        for (int t = 0; t < 4; t++) {
#pragma unroll
            for (int half = 0; half < 2; half++) {
                int nt = 2 * t + half;
                float p0 = ex2(s[nt][0] - mn0), p1 = ex2(s[nt][1] - mn0);
                float p2 = ex2(s[nt][2] - mn1), p3 = ex2(s[nt][3] - mn1);
                ps0 += p0 + p1; ps1 += p2 + p3;
                packpair(pah[t][2 * half],     pal[t][2 * half],     p0, p1);
                packpair(pah[t][2 * half + 1], pal[t][2 * half + 1], p2, p3);
            }
        }
        lac0 = lac0 * sc0 + ps0;
        lac1 = lac1 * sc1 + ps1;
#pragma unroll
        for (int n = 0; n < 4; n++) {
            o[n][0] *= sc0; o[n][1] *= sc0; o[n][2] *= sc1; o[n][3] *= sc1;
        }

        // ---- O += P V (bf16x3), V via trans ldmatrix ----
#pragma unroll
        for (int t = 0; t < 4; t++) {
#pragma unroll
            for (int np = 0; np < 2; np++) {
                uint32_t off = (uint32_t)(((t * 16 + (l & 15)) * 40 + np * 16 + (l >> 4) * 8) * 2);
                uint32_t vb[4], vbl[4];
                LDMX4T(vb[0], vb[1], vb[2], vb[3], aVh + off);
                LDMX4T(vbl[0], vbl[1], vbl[2], vbl[3], aVl + off);
                MMA16816(o[2 * np],     pah[t], vb[0],  vb[1]);
                MMA16816(o[2 * np],     pal[t], vb[0],  vb[1]);
                MMA16816(o[2 * np],     pah[t], vbl[0], vbl[1]);
                MMA16816(o[2 * np + 1], pah[t], vb[2],  vb[3]);
                MMA16816(o[2 * np + 1], pal[t], vb[2],  vb[3]);
                MMA16816(o[2 * np + 1], pah[t], vbl[2], vbl[3]);
            }
        }
        m0 = mn0; m1 = mn1;
    }

    lac0 += __shfl_xor_sync(0xffffffffu, lac0, 1);
    lac0 += __shfl_xor_sync(0xffffffffu, lac0, 2);
    lac1 += __shfl_xor_sync(0xffffffffu, lac1, 1);
    lac1 += __shfl_xor_sync(0xffffffffu, lac1, 2);
    float inv0 = 1.f / lac0, inv1 = 1.f / lac1;

#pragma unroll
    for (int nt = 0; nt < 4; nt++) {
        int col = nt * 8 + (l & 3) * 2;
        float v00 = o[nt][0] * inv0, v01 = o[nt][1] * inv0;
        float v10 = o[nt][2] * inv1, v11 = o[nt][3] * inv1;
        if (Of) {
            float2 a; a.x = v00; a.y = v01;
            float2 b; b.x = v10; b.y = v11;
            *reinterpret_cast<float2*>(&Of[base + (size_t)r0 * EMB + col]) = a;
            *reinterpret_cast<float2*>(&Of[base + (size_t)r1 * EMB + col]) = b;
        }
        if (Oh) {
            uint32_t h0, l0p, h1v, l1p;
            packpair(h0, l0p, v00, v01);
            packpair(h1v, l1p, v10, v11);
            *reinterpret_cast<uint32_t*>(&Oh[base + (size_t)r0 * EMB + col]) = h0;
            *reinterpret_cast<uint32_t*>(&Ol[base + (size_t)r0 * EMB + col]) = l0p;
            *reinterpret_cast<uint32_t*>(&Oh[base + (size_t)r1 * EMB + col]) = h1v;
            *reinterpret_cast<uint32_t*>(&Ol[base + (size_t)r1 * EMB + col]) = l1p;
        }
    }
}

// ---------------------------------------------------------------------------
// fp32 SGEMM (OUT head only, N=32)
// ---------------------------------------------------------------------------
__global__ __launch_bounds__(256) void sgemm_k(
    const float* __restrict__ A, const float* __restrict__ W,
    const float* __restrict__ bias, float* __restrict__ C,
    int M, int N, int K, int act)
{
    __shared__ float As[16][132];
    __shared__ float Ws[16][132];
    const int bm = blockIdx.y * 128;
    const int bn = blockIdx.x * 128;
    const int tid = threadIdx.x;
    const int tm = tid >> 4;
    const int tn = tid & 15;

    float acc[8][8];
#pragma unroll
    for (int x = 0; x < 8; x++)
#pragma unroll
        for (int y = 0; y < 8; y++) acc[x][y] = 0.f;

    for (int k0 = 0; k0 < K; k0 += 16) {
#pragma unroll
        for (int i = tid; i < 2048; i += 256) {
            int m = i >> 4, kk = i & 15;
            As[kk][m] = A[(size_t)(bm + m) * K + (k0 + kk)];
        }
#pragma unroll
        for (int i = tid; i < 2048; i += 256) {
            int kk = i >> 7, n = i & 127;
            int gn = bn + n;
            Ws[kk][n] = (gn < N) ? W[(size_t)(k0 + kk) * N + gn] : 0.f;
        }
        __syncthreads();
#pragma unroll
        for (int kk = 0; kk < 16; kk++) {
            float4 a0 = *reinterpret_cast<const float4*>(&As[kk][tm * 8]);
            float4 a1 = *reinterpret_cast<const float4*>(&As[kk][tm * 8 + 4]);
            float4 w0 = *reinterpret_cast<const float4*>(&Ws[kk][tn * 8]);
            float4 w1 = *reinterpret_cast<const float4*>(&Ws[kk][tn * 8 + 4]);
            float a[8] = {a0.x, a0.y, a0.z, a0.w, a1.x, a1.y, a1.z, a1.w};
            float w[8] = {w0.x, w0.y, w0.z, w0.w, w1.x, w1.y, w1.z, w1.w};
#pragma unroll
            for (int x = 0; x < 8; x++)
#pragma unroll
                for (int y = 0; y < 8; y++) acc[x][y] = fmaf(a[x], w[y], acc[x][y]);
        }
        __syncthreads();
    }

#pragma unroll
    for (int x = 0; x < 8; x++) {
        int gm = bm + tm * 8 + x;
#pragma unroll
        for (int y = 0; y < 8; y++) {
            int gn = bn + tn * 8 + y;
            if (gn < N) {
                float vv = acc[x][y] + bias[gn];
                if (act) vv = gelu_exact(vv);
                C[(size_t)gm * N + gn] = vv;
            }
        }
    }
}

// ---------------------------------------------------------------------------
// out = LayerNorm(A + B) * gamma + beta, row dim 128, eps 1e-5
// ---------------------------------------------------------------------------
__global__ void add_ln_k(const float* __restrict__ A, const float* __restrict__ Bv,
                         const float* __restrict__ gam, const float* __restrict__ bet,
                         float* __restrict__ out)
{
    int row = blockIdx.x;
    int d = threadIdx.x;  // 128
    float x = A[(size_t)row * 128 + d] + Bv[(size_t)row * 128 + d];

    __shared__ float ws[4], ws2[4];
    float v = x;
#pragma unroll
    for (int off = 16; off; off >>= 1) v += __shfl_xor_sync(0xffffffffu, v, off);
    if ((d & 31) == 0) ws[d >> 5] = v;
    __syncthreads();
    float mean = (ws[0] + ws[1] + ws[2] + ws[3]) * (1.f / 128.f);
    float dif = x - mean;
    float v2 = dif * dif;
#pragma unroll
    for (int off = 16; off; off >>= 1) v2 += __shfl_xor_sync(0xffffffffu, v2, off);
    if ((d & 31) == 0) ws2[d >> 5] = v2;
    __syncthreads();
    float var = (ws2[0] + ws2[1] + ws2[2] + ws2[3]) * (1.f / 128.f);
    out[(size_t)row * 128 + d] = dif * rsqrtf(var + 1e-5f) * gam[d] + bet[d];
}

// ---------------------------------------------------------------------------
extern "C" void kernel_launch(void* const* d_in, const int* in_sizes, int n_in,
                              void* d_out, int out_size)
{
    const float* kq    = (const float*)d_in[0];
    const float* v_in  = (const float*)d_in[1];
    const float* A_Wk  = (const float*)d_in[2];
    const float* A_bk  = (const float*)d_in[3];
    const float* A_Wq  = (const float*)d_in[4];
    const float* A_bq  = (const float*)d_in[5];
    const float* A_Wv  = (const float*)d_in[6];
    const float* A_bv  = (const float*)d_in[7];
    const float* A_f1W = (const float*)d_in[8];
    const float* A_f1b = (const float*)d_in[9];
    const float* A_f2W = (const float*)d_in[10];
    const float* A_f2b = (const float*)d_in[11];
    const float* A_n1g = (const float*)d_in[12];
    const float* A_n1b = (const float*)d_in[13];
    const float* A_n2g = (const float*)d_in[14];
    const float* A_n2b = (const float*)d_in[15];
    const float* B_Wk  = (const float*)d_in[16];
    const float* B_bk  = (const float*)d_in[17];
    const float* B_Wq  = (const float*)d_in[18];
    const float* B_bq  = (const float*)d_in[19];
    const float* B_Wv  = (const float*)d_in[20];
    const float* B_bv  = (const float*)d_in[21];
    const float* B_f1W = (const float*)d_in[22];
    const float* B_f1b = (const float*)d_in[23];
    const float* B_f2W = (const float*)d_in[24];
    const float* B_f2b = (const float*)d_in[25];
    const float* out_W = (const float*)d_in[26];
    const float* out_b = (const float*)d_in[27];
    float* out = (float*)d_out;

    float* pool = nullptr;
    cudaGetSymbolAddress((void**)&pool, g_scratch);

    typedef __nv_bfloat16 bf16;
    const size_t S = (size_t)R_TOTAL * 128;  // 2M floats per slot
    // fp32 slots
    float* Va    = pool + 0 * S;
    float* attnA = pool + 1 * S;
    float* h1    = pool + 2 * S;
    float* t1    = pool + 3 * S;
    float* vA    = pool + 4 * S;
    float* ffb   = pool + 5 * S;
    // bf16 slots (each slot = 4M bf16)
    bf16* sXh  = (bf16*)(pool + 6 * S);
    bf16* sXl  = (bf16*)(pool + 7 * S);
    bf16* Kah  = (bf16*)(pool + 8 * S);
    bf16* Kal  = (bf16*)(pool + 9 * S);
    bf16* Qah  = (bf16*)(pool + 10 * S);
    bf16* Qal  = (bf16*)(pool + 11 * S);
    bf16* Vah  = (bf16*)(pool + 12 * S);
    bf16* Val  = (bf16*)(pool + 13 * S);
    bf16* ffh  = (bf16*)(pool + 14 * S);   // 8M bf16 (slots 14-15)
    bf16* ffl  = (bf16*)(pool + 16 * S);   // 8M bf16 (slots 16-17)
    bf16* kqh  = (bf16*)(pool + 18 * S);
    bf16* kql  = (bf16*)(pool + 19 * S);
    bf16* at2h = (bf16*)(pool + 20 * S);
    bf16* at2l = (bf16*)(pool + 21 * S);
    bf16* wb   = (bf16*)(pool + 22 * S);
    bf16* aWk_h = wb;            bf16* aWk_l = wb + 16384;
    bf16* aWq_h = wb + 32768;    bf16* aWq_l = wb + 49152;
    bf16* aWv_h = wb + 65536;    bf16* aWv_l = wb + 81920;
    bf16* af1_h = wb + 98304;    bf16* af1_l = af1_h + 65536;
    bf16* af2_h = af1_l + 65536; bf16* af2_l = af2_h + 65536;
    bf16* bWk_h = af2_l + 65536; bf16* bWk_l = bWk_h + 8192;
    bf16* bWq_h = bWk_l + 8192;  bf16* bWq_l = bWq_h + 8192;
    bf16* bWv_h = bWq_l + 8192;  bf16* bWv_l = bWv_h + 16384;
    bf16* bf1_h = bWv_l + 16384; bf16* bf1_l = bf1_h + 65536;
    bf16* bf2_h = bf1_l + 65536; bf16* bf2_l = bf2_h + 65536;

    dim3 blk256(256);
    dim3 gN128(1, R_TOTAL / 128);
    dim3 gN512(4, R_TOTAL / 128);
    dim3 attnGrid(T_SEQ / 64, 8 * NHEAD);

    // ---- weight transforms ----
    tsplit_k<<<(128*128+255)/256, 256>>>(A_Wk, aWk_h, aWk_l, 128, 128);
    tsplit_k<<<(128*128+255)/256, 256>>>(A_Wq, aWq_h, aWq_l, 128, 128);
    tsplit_k<<<(128*128+255)/256, 256>>>(A_Wv, aWv_h, aWv_l, 128, 128);
    tsplit_k<<<(128*512+255)/256, 256>>>(A_f1W, af1_h, af1_l, 128, 512);
    tsplit_k<<<(512*128+255)/256, 256>>>(A_f2W, af2_h, af2_l, 512, 128);
    tsplit_k<<<(64*128+255)/256, 256>>>(B_Wk, bWk_h, bWk_l, 64, 128);
    tsplit_k<<<(64*128+255)/256, 256>>>(B_Wq, bWq_h, bWq_l, 64, 128);
    tsplit_k<<<(128*128+255)/256, 256>>>(B_Wv, bWv_h, bWv_l, 128, 128);
    tsplit_k<<<(128*512+255)/256, 256>>>(B_f1W, bf1_h, bf1_l, 128, 512);
    tsplit_k<<<(512*128+255)/256, 256>>>(B_f2W, bf2_h, bf2_l, 512, 128);

    // ---- Layer A ----
    splitcat_k<<<(R_TOTAL*32+255)/256, 256>>>(kq, v_in, sXh, sXl);
    mma_gemm<<<gN128, blk256>>>(sXh, sXl, aWk_h, aWk_l, A_bk, nullptr, Kah, Kal, 128, 128, 0, 1.f);
    mma_gemm<<<gN128, blk256>>>(sXh, sXl, aWq_h, aWq_l, A_bq, nullptr, Qah, Qal, 128, 128, 0, LOG2E);
    mma_gemm<<<gN128, blk256>>>(sXh, sXl, aWv_h, aWv_l, A_bv, Va, Vah, Val, 128, 128, 0, 1.f);
    attn_tc<<<attnGrid, 128>>>(Qah, Qal, Kah, Kal, Vah, Val, attnA, nullptr, nullptr, 0);
    add_ln_k<<<R_TOTAL, 128>>>(Va, attnA, A_n1g, A_n1b, h1);
    split_k<<<(R_TOTAL*32+255)/256, 256>>>(h1, sXh, sXl, R_TOTAL*32);
    mma_gemm<<<gN512, blk256>>>(sXh, sXl, af1_h, af1_l, A_f1b, nullptr, ffh, ffl, 128, 512, 1, 1.f);
    mma_gemm<<<gN128, blk256>>>(ffh, ffl, af2_h, af2_l, A_f2b, t1, nullptr, nullptr, 512, 128, 0, 1.f);
    add_ln_k<<<R_TOTAL, 128>>>(h1, t1, A_n2g, A_n2b, vA);

    // ---- Layer B ----
    split_k<<<(R_TOTAL*16+255)/256, 256>>>(kq, kqh, kql, R_TOTAL*16);
    mma_gemm<<<gN128, blk256>>>(kqh, kql, bWk_h, bWk_l, B_bk, nullptr, Kah, Kal, 64, 128, 0, 1.f);
    mma_gemm<<<gN128, blk256>>>(kqh, kql, bWq_h, bWq_l, B_bq, nullptr, Qah, Qal, 64, 128, 0, LOG2E);
    split_k<<<(R_TOTAL*32+255)/256, 256>>>(vA, sXh, sXl, R_TOTAL*32);
    mma_gemm<<<gN128, blk256>>>(sXh, sXl, bWv_h, bWv_l, B_bv, nullptr, Vah, Val, 128, 128, 0, 1.f);
    attn_tc<<<attnGrid, 128>>>(Qah, Qal, Kah, Kal, Vah, Val, nullptr, at2h, at2l, 1);
    mma_gemm<<<gN512, blk256>>>(at2h, at2l, bf1_h, bf1_l, B_f1b, nullptr, ffh, ffl, 128, 512, 1, 1.f);
    mma_gemm<<<gN128, blk256>>>(ffh, ffl, bf2_h, bf2_l, B_f2b, ffb, nullptr, nullptr, 512, 128, 0, 1.f);

    // ---- OUT head (fp32, N=32) ----
    sgemm_k<<<dim3(1, R_TOTAL / 128), blk256>>>(ffb, out_W, out_b, out, R_TOTAL, 32, 128, 0);
}